// round 6
// baseline (speedup 1.0000x reference)
#include <cuda_runtime.h>
#include <math.h>
#include <stdint.h>

#define TT 2048
#define DIM 2048
#define NEXP 32
#define TOPK 4
#define INTER 1024
#define SHIN 2048
#define NA (TT*TOPK)
#define BM 128
#define MAXTILES (NA/BM + NEXP)   /* 96 */
#define PADS 36                   /* smem row stride in floats */

// ---------------- device scratch ----------------
__device__ int   g_topi[TT*TOPK];
__device__ float g_topw[TT*TOPK];
__device__ int   g_cnt[NEXP];
__device__ int   g_off[NEXP+1];
__device__ int   g_tok[NA];
__device__ float g_wt[NA];
__device__ int   g_tile_e[MAXTILES];
__device__ int   g_tile_r0[MAXTILES];
__device__ int   g_tile_n[MAXTILES];
__device__ int   g_ntiles;
__device__ float g_h[(size_t)NA*INTER];
__device__ float g_hs[(size_t)TT*SHIN];

// ---------------- helpers ----------------
__device__ __forceinline__ uint32_t smem_u32(const void* p) {
    uint32_t a;
    asm("{ .reg .u64 t; cvta.to.shared.u64 t, %1; cvt.u32.u64 %0, t; }" : "=r"(a) : "l"(p));
    return a;
}
__device__ __forceinline__ uint32_t f2tf(float f) {
    uint32_t r; asm("cvt.rna.tf32.f32 %0, %1;" : "=r"(r) : "f"(f)); return r;
}
__device__ __forceinline__ void cp16(uint32_t dst, const void* src) {
    asm volatile("cp.async.cg.shared.global [%0], [%1], 16;" :: "r"(dst), "l"(src));
}
#define CP_COMMIT() asm volatile("cp.async.commit_group;" ::: "memory")
template<int N>
__device__ __forceinline__ void cp_wait() {
    asm volatile("cp.async.wait_group %0;" :: "n"(N) : "memory");
}
__device__ __forceinline__ void mma8(float* c, const uint32_t* a, const uint32_t* b) {
    asm volatile("mma.sync.aligned.m16n8k8.row.col.f32.tf32.tf32.f32 "
        "{%0,%1,%2,%3}, {%4,%5,%6,%7}, {%8,%9}, {%0,%1,%2,%3};"
        : "+f"(c[0]), "+f"(c[1]), "+f"(c[2]), "+f"(c[3])
        : "r"(a[0]), "r"(a[1]), "r"(a[2]), "r"(a[3]), "r"(b[0]), "r"(b[1]));
}
__device__ __forceinline__ float silu_f(float v) { return v / (1.0f + __expf(-v)); }

// ---------------- kernel 0: zero counters ----------------
__global__ void k_zero() {
    if (threadIdx.x < NEXP) g_cnt[threadIdx.x] = 0;
}

// ---------------- kernel 1: gate (fp32 exact) ----------------
__global__ __launch_bounds__(128) void k_gate(const float* __restrict__ x,
                                              const float* __restrict__ gw) {
    __shared__ float sx[DIM];
    __shared__ float slog[NEXP];
    int t = blockIdx.x;
    const float* xr = x + (size_t)t * DIM;
    for (int i = threadIdx.x * 4; i < DIM; i += 128 * 4)
        *(float4*)(sx + i) = *(const float4*)(xr + i);
    __syncthreads();

    int e = threadIdx.x >> 2, part = threadIdx.x & 3;
    const float* wr = gw + (size_t)e * DIM;
    float s = 0.f;
    for (int k = part * 4; k < DIM; k += 16) {
        float4 a = *(const float4*)(sx + k);
        float4 b = *(const float4*)(wr + k);
        s += a.x * b.x + a.y * b.y + a.z * b.z + a.w * b.w;
    }
    s += __shfl_down_sync(0xffffffffu, s, 2, 4);
    s += __shfl_down_sync(0xffffffffu, s, 1, 4);
    if (part == 0) slog[e] = s;
    __syncthreads();

    if (threadIdx.x < 32) {
        float sc = slog[threadIdx.x];
        float m = sc;
        for (int o = 16; o; o >>= 1) m = fmaxf(m, __shfl_xor_sync(0xffffffffu, m, o));
        float p = expf(sc - m);
        float sum = p;
        for (int o = 16; o; o >>= 1) sum += __shfl_xor_sync(0xffffffffu, sum, o);
        float v = p / sum;
        for (int r = 0; r < TOPK; r++) {
            float mv = v;
            for (int o = 16; o; o >>= 1) mv = fmaxf(mv, __shfl_xor_sync(0xffffffffu, mv, o));
            unsigned bal = __ballot_sync(0xffffffffu, v == mv);
            int idx = __ffs(bal) - 1;
            if (threadIdx.x == 0) {
                g_topi[t * TOPK + r] = idx;
                g_topw[t * TOPK + r] = mv;
                atomicAdd(&g_cnt[idx], 1);
            }
            if (threadIdx.x == idx) v = -1.f;
        }
    }
}

// ---------------- kernel 2: offsets + tile map ----------------
__global__ void k_build() {
    if (threadIdx.x == 0) {
        int off = 0;
        for (int e = 0; e < NEXP; e++) { g_off[e] = off; off += g_cnt[e]; }
        g_off[NEXP] = off;
        int nt = 0;
        for (int e = 0; e < NEXP; e++) {
            int n = g_cnt[e], base = g_off[e];
            for (int r0 = 0; r0 < n; r0 += BM) {
                g_tile_e[nt] = e; g_tile_r0[nt] = base + r0;
                g_tile_n[nt] = min(BM, n - r0); nt++;
            }
        }
        g_ntiles = nt;
    }
}

// ---------------- kernel 3: parallel deterministic scatter ----------------
__global__ __launch_bounds__(256) void k_scatter() {
    int e = blockIdx.x, tid = threadIdx.x, w = tid >> 5, lane = tid & 31;
    __shared__ int wc[8];
    int t0 = w * 256;
    int cnt = 0;
    for (int i = 0; i < 8; i++) {
        int t = t0 + i * 32 + lane;
        bool f = false;
        #pragma unroll
        for (int k = 0; k < TOPK; k++) if (g_topi[t * TOPK + k] == e) f = true;
        cnt += __popc(__ballot_sync(0xffffffffu, f));
    }
    if (lane == 0) wc[w] = cnt;
    __syncthreads();
    int base = g_off[e];
    for (int ww = 0; ww < w; ww++) base += wc[ww];
    for (int i = 0; i < 8; i++) {
        int t = t0 + i * 32 + lane;
        float wt = 0.f; bool f = false;
        #pragma unroll
        for (int k = 0; k < TOPK; k++)
            if (g_topi[t * TOPK + k] == e) { f = true; wt = g_topw[t * TOPK + k]; }
        unsigned bal = __ballot_sync(0xffffffffu, f);
        int pos = base + __popc(bal & ((1u << lane) - 1u));
        if (f) { g_tok[pos] = t; g_wt[pos] = wt; }
        base += __popc(bal);
    }
}

// ---------------- up kernel: 128 x 128 tile, 512 thr, 3-stage -------------
// B tile: 256 rows (128 w1-cols + 128 w3-cols). Warps 4x4; warp 32x32 (x2 mats).
template<bool SHARED>
__global__ __launch_bounds__(512, 1) void k_up_mma(const float* __restrict__ x,
                                                   const float* __restrict__ w1,
                                                   const float* __restrict__ w3) {
    constexpr int NI = SHARED ? SHIN : INTER;
    constexpr int KC = 32;
    constexpr int NCH = DIM / KC;             // 64
    constexpr int ATILE = BM * PADS;
    constexpr int STAGE = (BM + 256) * PADS;  // A 128 rows + B 256 rows

    extern __shared__ float sm[];
    __shared__ int s_tok[BM];

    int tile = blockIdx.x;
    int e = 0, r0, nvalid = BM;
    if (!SHARED) {
        if (tile >= g_ntiles) return;
        e = g_tile_e[tile]; r0 = g_tile_r0[tile]; nvalid = g_tile_n[tile];
    } else r0 = tile * BM;

    int tid = threadIdx.x, wid = tid >> 5, lane = tid & 31;
    int jblk = blockIdx.y * 128;
    int wm = wid & 3, wn = wid >> 2;          // 4 x 4 warps
    int gq = lane >> 2, cq = lane & 3;

    if (tid < BM)
        s_tok[tid] = SHARED ? (r0 + tid) : g_tok[r0 + min(tid, nvalid - 1)];
    __syncthreads();

    // loader: 6 x 16B segments per thread per chunk (3072 slots / 512 thr)
    const float* gp[6];
    uint32_t so[6];
    uint32_t smu = smem_u32(sm);
    #pragma unroll
    for (int j = 0; j < 6; j++) {
        int id = tid + j * 512;
        int s = id & 7;
        if (id < 1024) {                       // A: 128 rows
            int r = id >> 3;
            so[j] = (uint32_t)(r * PADS + s * 4);
            gp[j] = x + (size_t)s_tok[r] * DIM + s * 4;
        } else {                               // B: 256 rows
            int rb = (id - 1024) >> 3;
            so[j] = (uint32_t)(ATILE + rb * PADS + s * 4);
            if (rb < 128) gp[j] = w1 + ((size_t)e * NI + jblk + rb) * DIM + s * 4;
            else          gp[j] = w3 + ((size_t)e * NI + jblk + (rb - 128)) * DIM + s * 4;
        }
    }

    float acc1[2][4][4], acc3[2][4][4];
    #pragma unroll
    for (int i = 0; i < 2; i++)
        #pragma unroll
        for (int j = 0; j < 4; j++)
            #pragma unroll
            for (int q = 0; q < 4; q++) { acc1[i][j][q] = 0.f; acc3[i][j][q] = 0.f; }

    // prologue: stages 0, 1
    #pragma unroll
    for (int j = 0; j < 6; j++) cp16(smu + so[j] * 4, gp[j]);
    CP_COMMIT();
    #pragma unroll
    for (int j = 0; j < 6; j++) cp16(smu + (STAGE + so[j]) * 4, gp[j] + KC);
    CP_COMMIT();

    int stc = 0;                               // stage of chunk c
    for (int c = 0; c < NCH; c++) {
        cp_wait<1>();
        __syncthreads();

        const float* sA = sm + stc * STAGE;
        const float* sB = sA + ATILE;

        #pragma unroll
        for (int ks = 0; ks < 4; ks++) {
            int kb = ks * 8;
            uint32_t a[2][4];
            #pragma unroll
            for (int i = 0; i < 2; i++) {
                int row = wm * 32 + i * 16 + gq;
                a[i][0] = f2tf(sA[row * PADS + kb + cq]);
                a[i][1] = f2tf(sA[(row + 8) * PADS + kb + cq]);
                a[i][2] = f2tf(sA[row * PADS + kb + 4 + cq]);
                a[i][3] = f2tf(sA[(row + 8) * PADS + kb + 4 + cq]);
            }
            uint32_t b1[4][2], b3[4][2];
            #pragma unroll
            for (int j = 0; j < 4; j++) {
                int nc = wn * 32 + j * 8 + gq;
                b1[j][0] = f2tf(sB[nc * PADS + kb + cq]);
                b1[j][1] = f2tf(sB[nc * PADS + kb + 4 + cq]);
                b3[j][0] = f2tf(sB[(128 + nc) * PADS + kb + cq]);
                b3[j][1] = f2tf(sB[(128 + nc) * PADS + kb + 4 + cq]);
            }
            #pragma unroll
            for (int i = 0; i < 2; i++)
                #pragma unroll
                for (int j = 0; j < 4; j++) {
                    mma8(acc1[i][j], a[i], b1[j]);
                    mma8(acc3[i][j], a[i], b3[j]);
                }
        }

        int cn = c + 2;
        if (cn < NCH) {
            int stn = (stc + 2 >= 3) ? (stc - 1) : (stc + 2);
            int kb = cn * KC;
            #pragma unroll
            for (int j = 0; j < 6; j++)
                cp16(smu + (stn * STAGE + so[j]) * 4, gp[j] + kb);
        }
        CP_COMMIT();
        stc = (stc + 1 == 3) ? 0 : (stc + 1);
    }

    #pragma unroll
    for (int i = 0; i < 2; i++) {
        int rbase = wm * 32 + i * 16 + gq;
        #pragma unroll
        for (int j = 0; j < 4; j++) {
            int col = jblk + wn * 32 + j * 8 + 2 * cq;
            if (rbase < nvalid) {
                float2 o;
                o.x = silu_f(acc1[i][j][0]) * acc3[i][j][0];
                o.y = silu_f(acc1[i][j][1]) * acc3[i][j][1];
                float* dst = SHARED ? (g_hs + (size_t)(r0 + rbase) * SHIN + col)
                                    : (g_h  + (size_t)(r0 + rbase) * INTER + col);
                *(float2*)dst = o;
            }
            if (rbase + 8 < nvalid) {
                float2 o;
                o.x = silu_f(acc1[i][j][2]) * acc3[i][j][2];
                o.y = silu_f(acc1[i][j][3]) * acc3[i][j][3];
                float* dst = SHARED ? (g_hs + (size_t)(r0 + rbase + 8) * SHIN + col)
                                    : (g_h  + (size_t)(r0 + rbase + 8) * INTER + col);
                *(float2*)dst = o;
            }
        }
    }
}

// ---------------- down kernel: 128 x 256 tile, 512 thr, 3-stage -----------
// Warps 4x4; warp 32x64.
template<bool SHARED>
__global__ __launch_bounds__(512, 1) void k_down_mma(const float* __restrict__ w2,
                                                     float* __restrict__ out) {
    constexpr int KD = SHARED ? SHIN : INTER;
    constexpr int KC = 32;
    constexpr int NCH = KD / KC;
    constexpr int ATILE = BM * PADS;
    constexpr int STAGE = (BM + 256) * PADS;

    extern __shared__ float sm[];
    __shared__ int   s_tok[BM];
    __shared__ float s_wtv[BM];

    int tile = blockIdx.x;
    int e = 0, r0, nvalid = BM;
    if (!SHARED) {
        if (tile >= g_ntiles) return;
        e = g_tile_e[tile]; r0 = g_tile_r0[tile]; nvalid = g_tile_n[tile];
    } else r0 = tile * BM;

    int tid = threadIdx.x, wid = tid >> 5, lane = tid & 31;
    int dblk = blockIdx.y * 256;
    int wm = wid & 3, wn = wid >> 2;
    int gq = lane >> 2, cq = lane & 3;

    if (tid < BM) {
        if (SHARED) { s_tok[tid] = r0 + tid; s_wtv[tid] = 1.f; }
        else {
            int ok = tid < nvalid;
            s_tok[tid] = ok ? g_tok[r0 + tid] : 0;
            s_wtv[tid] = ok ? g_wt[r0 + tid]  : 0.f;
        }
    }
    __syncthreads();

    const float* gp[6];
    uint32_t so[6];
    uint32_t smu = smem_u32(sm);
    #pragma unroll
    for (int j = 0; j < 6; j++) {
        int id = tid + j * 512;
        int s = id & 7;
        if (id < 1024) {
            int r = id >> 3;
            so[j] = (uint32_t)(r * PADS + s * 4);
            gp[j] = SHARED ? (g_hs + (size_t)(r0 + r) * SHIN + s * 4)
                           : (g_h + (size_t)min(r0 + r, NA - 1) * INTER + s * 4);
        } else {
            int rb = (id - 1024) >> 3;
            so[j] = (uint32_t)(ATILE + rb * PADS + s * 4);
            gp[j] = w2 + ((size_t)e * DIM + dblk + rb) * KD + s * 4;
        }
    }

    float acc[2][8][4];
    #pragma unroll
    for (int i = 0; i < 2; i++)
        #pragma unroll
        for (int j = 0; j < 8; j++)
            #pragma unroll
            for (int q = 0; q < 4; q++) acc[i][j][q] = 0.f;

    #pragma unroll
    for (int j = 0; j < 6; j++) cp16(smu + so[j] * 4, gp[j]);
    CP_COMMIT();
    #pragma unroll
    for (int j = 0; j < 6; j++) cp16(smu + (STAGE + so[j]) * 4, gp[j] + KC);
    CP_COMMIT();

    int stc = 0;
    for (int c = 0; c < NCH; c++) {
        cp_wait<1>();
        __syncthreads();

        const float* sA = sm + stc * STAGE;
        const float* sB = sA + ATILE;

        #pragma unroll
        for (int ks = 0; ks < 4; ks++) {
            int kb = ks * 8;
            uint32_t a[2][4];
            #pragma unroll
            for (int i = 0; i < 2; i++) {
                int row = wm * 32 + i * 16 + gq;
                a[i][0] = f2tf(sA[row * PADS + kb + cq]);
                a[i][1] = f2tf(sA[(row + 8) * PADS + kb + cq]);
                a[i][2] = f2tf(sA[row * PADS + kb + 4 + cq]);
                a[i][3] = f2tf(sA[(row + 8) * PADS + kb + 4 + cq]);
            }
            #pragma unroll
            for (int j = 0; j < 8; j++) {
                int nc = wn * 64 + j * 8 + gq;
                uint32_t b[2];
                b[0] = f2tf(sB[nc * PADS + kb + cq]);
                b[1] = f2tf(sB[nc * PADS + kb + 4 + cq]);
                mma8(acc[0][j], a[0], b);
                mma8(acc[1][j], a[1], b);
            }
        }

        int cn = c + 2;
        if (cn < NCH) {
            int stn = (stc + 2 >= 3) ? (stc - 1) : (stc + 2);
            int kb = cn * KC;
            #pragma unroll
            for (int j = 0; j < 6; j++)
                cp16(smu + (stn * STAGE + so[j]) * 4, gp[j] + kb);
        }
        CP_COMMIT();
        stc = (stc + 1 == 3) ? 0 : (stc + 1);
    }

    #pragma unroll
    for (int i = 0; i < 2; i++) {
        int rbase = wm * 32 + i * 16 + gq;
        #pragma unroll
        for (int j = 0; j < 8; j++) {
            int col = dblk + wn * 64 + j * 8 + 2 * cq;
            #pragma unroll
            for (int half = 0; half < 2; half++) {
                int r = rbase + half * 8;
                if (r >= nvalid) continue;
                int tok = s_tok[r];
                float wt = s_wtv[r];
                float* dst = out + (size_t)tok * DIM + col;
                float v0 = acc[i][j][half * 2 + 0];
                float v1 = acc[i][j][half * 2 + 1];
                if (SHARED) {
                    float2 o; o.x = v0; o.y = v1;
                    *(float2*)dst = o;
                } else {
                    atomicAdd(dst + 0, v0 * wt);
                    atomicAdd(dst + 1, v1 * wt);
                }
            }
        }
    }
}

// ---------------- launch ----------------
extern "C" void kernel_launch(void* const* d_in, const int* in_sizes, int n_in,
                              void* d_out, int out_size) {
    const float* x   = (const float*)d_in[0];
    const float* gw  = (const float*)d_in[1];
    const float* w1  = (const float*)d_in[2];
    const float* w2  = (const float*)d_in[3];
    const float* w3  = (const float*)d_in[4];
    const float* sw1 = (const float*)d_in[5];
    const float* sw2 = (const float*)d_in[6];
    const float* sw3 = (const float*)d_in[7];
    float* out = (float*)d_out;

    const int smBytes = 3 * (BM + 256) * PADS * 4;   // 165888
    cudaFuncSetAttribute((const void*)k_up_mma<false>,   cudaFuncAttributeMaxDynamicSharedMemorySize, smBytes);
    cudaFuncSetAttribute((const void*)k_up_mma<true>,    cudaFuncAttributeMaxDynamicSharedMemorySize, smBytes);
    cudaFuncSetAttribute((const void*)k_down_mma<false>, cudaFuncAttributeMaxDynamicSharedMemorySize, smBytes);
    cudaFuncSetAttribute((const void*)k_down_mma<true>,  cudaFuncAttributeMaxDynamicSharedMemorySize, smBytes);

    k_zero<<<1, 32>>>();
    k_gate<<<TT, 128>>>(x, gw);
    k_build<<<1, 1>>>();
    k_scatter<<<NEXP, 256>>>();

    k_up_mma<false><<<dim3(MAXTILES, INTER / 128), 512, smBytes>>>(x, w1, w3);
    k_up_mma<true><<<dim3(TT / BM, SHIN / 128), 512, smBytes>>>(x, sw1, sw3);

    k_down_mma<true><<<dim3(TT / BM, DIM / 256), 512, smBytes>>>(sw2, out);
    k_down_mma<false><<<dim3(MAXTILES, DIM / 256), 512, smBytes>>>(w2, out);
}

// round 7
// speedup vs baseline: 1.2312x; 1.2312x over previous
#include <cuda_runtime.h>
#include <math.h>
#include <stdint.h>

#define TT 2048
#define DIM 2048
#define NEXP 32
#define TOPK 4
#define INTER 1024
#define SHIN 2048
#define NA (TT*TOPK)
#define BM 128
#define MAXTILES (NA/BM + NEXP)   /* 96 */
#define PADS 36

#define UP_RB   (MAXTILES * 16)   /* routed up blocks: 96 tiles x 16 jblks(64) */
#define UP_SB   (16 * 32)         /* shared up blocks: 16 tiles x 32 jblks(64) */
#define DN_RB   (MAXTILES * 16)   /* routed down: 96 tiles x 16 dblks(128) */
#define DN_SB   (16 * 16)         /* shared down: 16 tiles x 16 dblks(128) */

// ---------------- device scratch ----------------
__device__ int   g_topi[TT*TOPK];
__device__ float g_topw[TT*TOPK];
__device__ int   g_cnt[NEXP];
__device__ int   g_off[NEXP+1];
__device__ int   g_tok[NA];
__device__ float g_wt[NA];
__device__ int   g_tile_e[MAXTILES];
__device__ int   g_tile_r0[MAXTILES];
__device__ int   g_tile_n[MAXTILES];
__device__ int   g_ntiles;
__device__ float g_h[(size_t)NA*INTER];
__device__ float g_hs[(size_t)TT*SHIN];

// ---------------- helpers ----------------
__device__ __forceinline__ uint32_t smem_u32(const void* p) {
    uint32_t a;
    asm("{ .reg .u64 t; cvta.to.shared.u64 t, %1; cvt.u32.u64 %0, t; }" : "=r"(a) : "l"(p));
    return a;
}
__device__ __forceinline__ uint32_t f2tf(float f) {
    uint32_t r; asm("cvt.rna.tf32.f32 %0, %1;" : "=r"(r) : "f"(f)); return r;
}
__device__ __forceinline__ uint32_t b2tf(uint32_t b) {
    uint32_t r; asm("cvt.rna.tf32.f32 %0, %1;" : "=r"(r) : "f"(__uint_as_float(b))); return r;
}
__device__ __forceinline__ void cp16(uint32_t dst, const void* src) {
    asm volatile("cp.async.cg.shared.global [%0], [%1], 16;" :: "r"(dst), "l"(src));
}
#define CP_COMMIT() asm volatile("cp.async.commit_group;" ::: "memory")
template<int N>
__device__ __forceinline__ void cp_wait() {
    asm volatile("cp.async.wait_group %0;" :: "n"(N) : "memory");
}
__device__ __forceinline__ void mma8(float* c, const uint32_t* a, const uint32_t* b) {
    asm volatile("mma.sync.aligned.m16n8k8.row.col.f32.tf32.tf32.f32 "
        "{%0,%1,%2,%3}, {%4,%5,%6,%7}, {%8,%9}, {%0,%1,%2,%3};"
        : "+f"(c[0]), "+f"(c[1]), "+f"(c[2]), "+f"(c[3])
        : "r"(a[0]), "r"(a[1]), "r"(a[2]), "r"(a[3]), "r"(b[0]), "r"(b[1]));
}
__device__ __forceinline__ void ldsm4(uint32_t* r, uint32_t addr) {
    asm volatile("ldmatrix.sync.aligned.m8n8.x4.shared.b16 {%0,%1,%2,%3}, [%4];"
        : "=r"(r[0]), "=r"(r[1]), "=r"(r[2]), "=r"(r[3]) : "r"(addr));
}
__device__ __forceinline__ float silu_f(float v) { return v / (1.0f + __expf(-v)); }

// ---------------- kernel 0: zero counters ----------------
__global__ void k_zero() {
    if (threadIdx.x < NEXP) g_cnt[threadIdx.x] = 0;
}

// ---------------- kernel 0b: zero output ----------------
__global__ __launch_bounds__(256) void k_zero_out(float* __restrict__ out) {
    int i = (blockIdx.x * 256 + threadIdx.x) * 4;
    float4 z = make_float4(0.f, 0.f, 0.f, 0.f);
    *(float4*)(out + i) = z;
}

// ---------------- kernel 1: gate (fp32 exact) ----------------
__global__ __launch_bounds__(128) void k_gate(const float* __restrict__ x,
                                              const float* __restrict__ gw) {
    __shared__ float sx[DIM];
    __shared__ float slog[NEXP];
    int t = blockIdx.x;
    const float* xr = x + (size_t)t * DIM;
    for (int i = threadIdx.x * 4; i < DIM; i += 128 * 4)
        *(float4*)(sx + i) = *(const float4*)(xr + i);
    __syncthreads();

    int e = threadIdx.x >> 2, part = threadIdx.x & 3;
    const float* wr = gw + (size_t)e * DIM;
    float s = 0.f;
    for (int k = part * 4; k < DIM; k += 16) {
        float4 a = *(const float4*)(sx + k);
        float4 b = *(const float4*)(wr + k);
        s += a.x * b.x + a.y * b.y + a.z * b.z + a.w * b.w;
    }
    s += __shfl_down_sync(0xffffffffu, s, 2, 4);
    s += __shfl_down_sync(0xffffffffu, s, 1, 4);
    if (part == 0) slog[e] = s;
    __syncthreads();

    if (threadIdx.x < 32) {
        float sc = slog[threadIdx.x];
        float m = sc;
        for (int o = 16; o; o >>= 1) m = fmaxf(m, __shfl_xor_sync(0xffffffffu, m, o));
        float p = expf(sc - m);
        float sum = p;
        for (int o = 16; o; o >>= 1) sum += __shfl_xor_sync(0xffffffffu, sum, o);
        float v = p / sum;
        for (int r = 0; r < TOPK; r++) {
            float mv = v;
            for (int o = 16; o; o >>= 1) mv = fmaxf(mv, __shfl_xor_sync(0xffffffffu, mv, o));
            unsigned bal = __ballot_sync(0xffffffffu, v == mv);
            int idx = __ffs(bal) - 1;
            if (threadIdx.x == 0) {
                g_topi[t * TOPK + r] = idx;
                g_topw[t * TOPK + r] = mv;
                atomicAdd(&g_cnt[idx], 1);
            }
            if (threadIdx.x == idx) v = -1.f;
        }
    }
}

// ---------------- kernel 2: offsets + tile map ----------------
__global__ void k_build() {
    if (threadIdx.x == 0) {
        int off = 0;
        for (int e = 0; e < NEXP; e++) { g_off[e] = off; off += g_cnt[e]; }
        g_off[NEXP] = off;
        int nt = 0;
        for (int e = 0; e < NEXP; e++) {
            int n = g_cnt[e], base = g_off[e];
            for (int r0 = 0; r0 < n; r0 += BM) {
                g_tile_e[nt] = e; g_tile_r0[nt] = base + r0;
                g_tile_n[nt] = min(BM, n - r0); nt++;
            }
        }
        g_ntiles = nt;
    }
}

// ---------------- kernel 3: parallel deterministic scatter ----------------
__global__ __launch_bounds__(256) void k_scatter() {
    int e = blockIdx.x, tid = threadIdx.x, w = tid >> 5, lane = tid & 31;
    __shared__ int wc[8];
    int t0 = w * 256;
    int cnt = 0;
    for (int i = 0; i < 8; i++) {
        int t = t0 + i * 32 + lane;
        bool f = false;
        #pragma unroll
        for (int k = 0; k < TOPK; k++) if (g_topi[t * TOPK + k] == e) f = true;
        cnt += __popc(__ballot_sync(0xffffffffu, f));
    }
    if (lane == 0) wc[w] = cnt;
    __syncthreads();
    int base = g_off[e];
    for (int ww = 0; ww < w; ww++) base += wc[ww];
    for (int i = 0; i < 8; i++) {
        int t = t0 + i * 32 + lane;
        float wt = 0.f; bool f = false;
        #pragma unroll
        for (int k = 0; k < TOPK; k++)
            if (g_topi[t * TOPK + k] == e) { f = true; wt = g_topw[t * TOPK + k]; }
        unsigned bal = __ballot_sync(0xffffffffu, f);
        int pos = base + __popc(bal & ((1u << lane) - 1u));
        if (f) { g_tok[pos] = t; g_wt[pos] = wt; }
        base += __popc(bal);
    }
}

// ---------------- merged up kernel ----------------------------------------
// 256 thr, 2 CTA/SM, tile 128 x (64 w1 + 64 w3), 2-stage cp.async, ldmatrix.
__global__ __launch_bounds__(256, 2) void k_up(const float* __restrict__ x,
                                               const float* __restrict__ w1,
                                               const float* __restrict__ w3,
                                               const float* __restrict__ sw1,
                                               const float* __restrict__ sw3) {
    constexpr int KC = 32;
    constexpr int NCH = DIM / KC;             // 64
    constexpr int ATILE = BM * PADS;
    constexpr int STAGE = 2 * ATILE;

    extern __shared__ float sm[];
    __shared__ int s_tok[BM];

    int bid = blockIdx.x;
    int e = 0, r0, nvalid = BM, jblk;
    const float *pw1, *pw3;
    float* dstH; int dstride, ni;
    bool routed = bid < UP_RB;
    if (routed) {
        int tile = bid >> 4;
        if (tile >= g_ntiles) return;
        jblk = (bid & 15) * 64;
        e = g_tile_e[tile]; r0 = g_tile_r0[tile]; nvalid = g_tile_n[tile];
        pw1 = w1; pw3 = w3; dstH = g_h; dstride = INTER; ni = INTER;
    } else {
        int sid = bid - UP_RB;
        int tile = sid >> 5;
        jblk = (sid & 31) * 64;
        r0 = tile * BM;
        pw1 = sw1; pw3 = sw3; dstH = g_hs; dstride = SHIN; ni = SHIN;
    }

    int tid = threadIdx.x, wid = tid >> 5, lane = tid & 31;
    int wm = wid & 3, wn = wid >> 2;          // 4 x 2 warps
    int gq = lane >> 2, cq = lane & 3;

    if (tid < BM)
        s_tok[tid] = routed ? g_tok[r0 + min(tid, nvalid - 1)] : (r0 + tid);
    __syncthreads();

    const float* gp[8];
    uint32_t so[8];
    uint32_t smu = smem_u32(sm);
    #pragma unroll
    for (int j = 0; j < 8; j++) {
        int id = tid + j * 256;
        int m = id >> 10;
        int r = (id & 1023) >> 3;
        int s = id & 7;
        so[j] = (uint32_t)(m * ATILE + r * PADS + s * 4);
        if (m == 0) gp[j] = x + (size_t)s_tok[r] * DIM + s * 4;
        else if (r < 64) gp[j] = pw1 + ((size_t)e * ni + jblk + r) * DIM + s * 4;
        else             gp[j] = pw3 + ((size_t)e * ni + jblk + (r - 64)) * DIM + s * 4;
    }

    float acc1[2][4][4], acc3[2][4][4];
    #pragma unroll
    for (int i = 0; i < 2; i++)
        #pragma unroll
        for (int j = 0; j < 4; j++)
            #pragma unroll
            for (int q = 0; q < 4; q++) { acc1[i][j][q] = 0.f; acc3[i][j][q] = 0.f; }

    uint32_t aoff = (uint32_t)(((lane & 15) * PADS + ((lane & 16) ? 4 : 0)) * 4);
    uint32_t boff = (uint32_t)((((lane & 7) + ((lane & 16) ? 8 : 0)) * PADS
                               + ((lane & 8) ? 4 : 0)) * 4);

    #pragma unroll
    for (int j = 0; j < 8; j++) cp16(smu + so[j] * 4, gp[j]);
    CP_COMMIT();

    for (int c = 0; c < NCH; c++) {
        int st = c & 1;
        if (c + 1 < NCH) {
            int kb = (c + 1) * KC;
            #pragma unroll
            for (int j = 0; j < 8; j++)
                cp16(smu + ((st ^ 1) * STAGE + so[j]) * 4, gp[j] + kb);
            CP_COMMIT();
            cp_wait<1>();
        } else cp_wait<0>();
        __syncthreads();

        uint32_t stA = smu + (uint32_t)(st * STAGE) * 4;
        uint32_t stB = stA + (uint32_t)ATILE * 4;

        #pragma unroll
        for (int ks = 0; ks < 4; ks++) {
            int kb = ks * 8;
            uint32_t a[2][4];
            #pragma unroll
            for (int i = 0; i < 2; i++) {
                ldsm4(a[i], stA + (uint32_t)(((wm * 32 + i * 16) * PADS + kb) * 4) + aoff);
                #pragma unroll
                for (int q = 0; q < 4; q++) a[i][q] = b2tf(a[i][q]);
            }
            uint32_t b1[2][4], b3[2][4];
            #pragma unroll
            for (int j2 = 0; j2 < 2; j2++) {
                int nc0 = wn * 32 + j2 * 16;
                ldsm4(b1[j2], stB + (uint32_t)((nc0 * PADS + kb) * 4) + boff);
                ldsm4(b3[j2], stB + (uint32_t)(((64 + nc0) * PADS + kb) * 4) + boff);
                #pragma unroll
                for (int q = 0; q < 4; q++) {
                    b1[j2][q] = b2tf(b1[j2][q]);
                    b3[j2][q] = b2tf(b3[j2][q]);
                }
            }
            #pragma unroll
            for (int i = 0; i < 2; i++)
                #pragma unroll
                for (int j2 = 0; j2 < 2; j2++) {
                    mma8(acc1[i][j2 * 2 + 0], a[i], b1[j2] + 0);
                    mma8(acc1[i][j2 * 2 + 1], a[i], b1[j2] + 2);
                    mma8(acc3[i][j2 * 2 + 0], a[i], b3[j2] + 0);
                    mma8(acc3[i][j2 * 2 + 1], a[i], b3[j2] + 2);
                }
        }
        __syncthreads();
    }

    #pragma unroll
    for (int i = 0; i < 2; i++) {
        int rbase = wm * 32 + i * 16 + gq;
        #pragma unroll
        for (int j = 0; j < 4; j++) {
            int col = jblk + wn * 32 + j * 8 + 2 * cq;
            if (rbase < nvalid) {
                float2 o;
                o.x = silu_f(acc1[i][j][0]) * acc3[i][j][0];
                o.y = silu_f(acc1[i][j][1]) * acc3[i][j][1];
                *(float2*)(dstH + (size_t)(r0 + rbase) * dstride + col) = o;
            }
            if (rbase + 8 < nvalid) {
                float2 o;
                o.x = silu_f(acc1[i][j][2]) * acc3[i][j][2];
                o.y = silu_f(acc1[i][j][3]) * acc3[i][j][3];
                *(float2*)(dstH + (size_t)(r0 + rbase + 8) * dstride + col) = o;
            }
        }
    }
}

// ---------------- merged down kernel --------------------------------------
// 256 thr, 2 CTA/SM, tile 128 x 128. Output via atomicAdd into zeroed d_out.
__global__ __launch_bounds__(256, 2) void k_down(const float* __restrict__ w2,
                                                 const float* __restrict__ sw2,
                                                 float* __restrict__ out) {
    constexpr int KC = 32;
    constexpr int ATILE = BM * PADS;
    constexpr int STAGE = 2 * ATILE;

    extern __shared__ float sm[];
    __shared__ int   s_tok[BM];
    __shared__ float s_wtv[BM];

    int bid = blockIdx.x;
    int e = 0, r0, nvalid = BM, dblk, kd, nch;
    const float* srcH; int sstride;
    const float* pb;
    bool routed = bid < DN_RB;
    if (routed) {
        int tile = bid >> 4;
        if (tile >= g_ntiles) return;
        dblk = (bid & 15) * 128;
        e = g_tile_e[tile]; r0 = g_tile_r0[tile]; nvalid = g_tile_n[tile];
        srcH = g_h; sstride = INTER; kd = INTER; nch = INTER / KC;
        pb = w2;
    } else {
        int sid = bid - DN_RB;
        int tile = sid >> 4;
        dblk = (sid & 15) * 128;
        r0 = tile * BM;
        srcH = g_hs; sstride = SHIN; kd = SHIN; nch = SHIN / KC;
        pb = sw2;
    }

    int tid = threadIdx.x, wid = tid >> 5, lane = tid & 31;
    int wm = wid & 3, wn = wid >> 2;
    int gq = lane >> 2, cq = lane & 3;

    if (tid < BM) {
        if (routed) {
            int ok = tid < nvalid;
            s_tok[tid] = ok ? g_tok[r0 + tid] : 0;
            s_wtv[tid] = ok ? g_wt[r0 + tid]  : 0.f;
        } else { s_tok[tid] = r0 + tid; s_wtv[tid] = 1.f; }
    }
    __syncthreads();

    const float* gp[8];
    uint32_t so[8];
    uint32_t smu = smem_u32(sm);
    #pragma unroll
    for (int j = 0; j < 8; j++) {
        int id = tid + j * 256;
        int m = id >> 10;
        int r = (id & 1023) >> 3;
        int s = id & 7;
        so[j] = (uint32_t)(m * ATILE + r * PADS + s * 4);
        if (m == 0) gp[j] = srcH + (size_t)min(r0 + r, (routed ? NA : TT) - 1) * sstride + s * 4;
        else        gp[j] = pb + ((size_t)e * DIM + dblk + r) * kd + s * 4;
    }

    float acc[2][8][4];
    #pragma unroll
    for (int i = 0; i < 2; i++)
        #pragma unroll
        for (int j = 0; j < 8; j++)
            #pragma unroll
            for (int q = 0; q < 4; q++) acc[i][j][q] = 0.f;

    uint32_t aoff = (uint32_t)(((lane & 15) * PADS + ((lane & 16) ? 4 : 0)) * 4);
    uint32_t boff = (uint32_t)((((lane & 7) + ((lane & 16) ? 8 : 0)) * PADS
                               + ((lane & 8) ? 4 : 0)) * 4);

    #pragma unroll
    for (int j = 0; j < 8; j++) cp16(smu + so[j] * 4, gp[j]);
    CP_COMMIT();

    for (int c = 0; c < nch; c++) {
        int st = c & 1;
        if (c + 1 < nch) {
            int kb = (c + 1) * KC;
            #pragma unroll
            for (int j = 0; j < 8; j++)
                cp16(smu + ((st ^ 1) * STAGE + so[j]) * 4, gp[j] + kb);
            CP_COMMIT();
            cp_wait<1>();
        } else cp_wait<0>();
        __syncthreads();

        uint32_t stA = smu + (uint32_t)(st * STAGE) * 4;
        uint32_t stB = stA + (uint32_t)ATILE * 4;

        #pragma unroll
        for (int ks = 0; ks < 4; ks++) {
            int kb = ks * 8;
            uint32_t a[2][4];
            #pragma unroll
            for (int i = 0; i < 2; i++) {
                ldsm4(a[i], stA + (uint32_t)(((wm * 32 + i * 16) * PADS + kb) * 4) + aoff);
                #pragma unroll
                for (int q = 0; q < 4; q++) a[i][q] = b2tf(a[i][q]);
            }
            uint32_t b[4][4];
            #pragma unroll
            for (int j2 = 0; j2 < 4; j2++) {
                ldsm4(b[j2], stB + (uint32_t)(((wn * 64 + j2 * 16) * PADS + kb) * 4) + boff);
                #pragma unroll
                for (int q = 0; q < 4; q++) b[j2][q] = b2tf(b[j2][q]);
            }
            #pragma unroll
            for (int i = 0; i < 2; i++)
                #pragma unroll
                for (int j2 = 0; j2 < 4; j2++) {
                    mma8(acc[i][j2 * 2 + 0], a[i], b[j2] + 0);
                    mma8(acc[i][j2 * 2 + 1], a[i], b[j2] + 2);
                }
        }
        __syncthreads();
    }

    #pragma unroll
    for (int i = 0; i < 2; i++) {
        int rbase = wm * 32 + i * 16 + gq;
        #pragma unroll
        for (int j = 0; j < 8; j++) {
            int col = dblk + wn * 64 + j * 8 + 2 * cq;
            #pragma unroll
            for (int half = 0; half < 2; half++) {
                int r = rbase + half * 8;
                if (r >= nvalid) continue;
                int tok = s_tok[r];
                float wt = s_wtv[r];
                float* dst = out + (size_t)tok * DIM + col;
                atomicAdd(dst + 0, acc[i][j][half * 2 + 0] * wt);
                atomicAdd(dst + 1, acc[i][j][half * 2 + 1] * wt);
            }
        }
    }
}

// ---------------- launch ----------------
extern "C" void kernel_launch(void* const* d_in, const int* in_sizes, int n_in,
                              void* d_out, int out_size) {
    const float* x   = (const float*)d_in[0];
    const float* gw  = (const float*)d_in[1];
    const float* w1  = (const float*)d_in[2];
    const float* w2  = (const float*)d_in[3];
    const float* w3  = (const float*)d_in[4];
    const float* sw1 = (const float*)d_in[5];
    const float* sw2 = (const float*)d_in[6];
    const float* sw3 = (const float*)d_in[7];
    float* out = (float*)d_out;

    const int smBytes = 2 * 2 * BM * PADS * 4;   // 73728
    cudaFuncSetAttribute((const void*)k_up,   cudaFuncAttributeMaxDynamicSharedMemorySize, smBytes);
    cudaFuncSetAttribute((const void*)k_down, cudaFuncAttributeMaxDynamicSharedMemorySize, smBytes);

    k_zero<<<1, 32>>>();
    k_zero_out<<<(TT * DIM) / 1024, 256>>>(out);
    k_gate<<<TT, 128>>>(x, gw);
    k_build<<<1, 1>>>();
    k_scatter<<<NEXP, 256>>>();

    k_up<<<UP_RB + UP_SB, 256, smBytes>>>(x, w1, w3, sw1, sw3);
    k_down<<<DN_RB + DN_SB, 256, smBytes>>>(w2, sw2, out);
}

// round 8
// speedup vs baseline: 1.6532x; 1.3428x over previous
#include <cuda_runtime.h>
#include <math.h>
#include <stdint.h>

#define TT 2048
#define DIM 2048
#define NEXP 32
#define TOPK 4
#define INTER 1024
#define SHIN 2048
#define NA (TT*TOPK)
#define BM 128
#define MAXTILES (NA/BM + NEXP)   /* 96 */
#define PADS 32                   /* fp32 stage words/row */
#define PADH 20                   /* fp16 stage words/row (16 data + 4 pad) */
#define FWORDS (256*PADS)         /* 8192 words per fp32 stage */
#define HWORDS (256*PADH)         /* 5120 words per fp16 stage */
#define HBASE  (2*FWORDS)         /* word offset of fp16 region */

#define UP_RB   (MAXTILES * 16)
#define UP_SB   (16 * 32)
#define DN_RB   (MAXTILES * 16)
#define DN_SB   (16 * 16)

// ---------------- device scratch ----------------
__device__ int   g_topi[TT*TOPK];
__device__ float g_topw[TT*TOPK];
__device__ int   g_cnt[NEXP];
__device__ int   g_off[NEXP+1];
__device__ int   g_tok[NA];
__device__ float g_wt[NA];
__device__ int   g_tile_e[MAXTILES];
__device__ int   g_tile_r0[MAXTILES];
__device__ int   g_tile_n[MAXTILES];
__device__ int   g_ntiles;
__device__ float g_h[(size_t)NA*INTER];
__device__ float g_hs[(size_t)TT*SHIN];

// ---------------- helpers ----------------
__device__ __forceinline__ uint32_t smem_u32(const void* p) {
    uint32_t a;
    asm("{ .reg .u64 t; cvta.to.shared.u64 t, %1; cvt.u32.u64 %0, t; }" : "=r"(a) : "l"(p));
    return a;
}
__device__ __forceinline__ uint32_t pk16(float lo, float hi) {
    uint32_t r; asm("cvt.rn.f16x2.f32 %0, %1, %2;" : "=r"(r) : "f"(hi), "f"(lo)); return r;
}
__device__ __forceinline__ void cp16(uint32_t dst, const void* src) {
    asm volatile("cp.async.cg.shared.global [%0], [%1], 16;" :: "r"(dst), "l"(src));
}
#define CP_COMMIT() asm volatile("cp.async.commit_group;" ::: "memory")
template<int N>
__device__ __forceinline__ void cp_wait() {
    asm volatile("cp.async.wait_group %0;" :: "n"(N) : "memory");
}
__device__ __forceinline__ void mma16(float* c, const uint32_t* a, uint32_t b0, uint32_t b1) {
    asm volatile("mma.sync.aligned.m16n8k16.row.col.f32.f16.f16.f32 "
        "{%0,%1,%2,%3}, {%4,%5,%6,%7}, {%8,%9}, {%0,%1,%2,%3};"
        : "+f"(c[0]), "+f"(c[1]), "+f"(c[2]), "+f"(c[3])
        : "r"(a[0]), "r"(a[1]), "r"(a[2]), "r"(a[3]), "r"(b0), "r"(b1));
}
__device__ __forceinline__ void ldsm4(uint32_t* r, uint32_t addr) {
    asm volatile("ldmatrix.sync.aligned.m8n8.x4.shared.b16 {%0,%1,%2,%3}, [%4];"
        : "=r"(r[0]), "=r"(r[1]), "=r"(r[2]), "=r"(r[3]) : "r"(addr));
}
__device__ __forceinline__ float silu_f(float v) { return v / (1.0f + __expf(-v)); }

// ---------------- kernel 0: zero counters ----------------
__global__ void k_zero() {
    if (threadIdx.x < NEXP) g_cnt[threadIdx.x] = 0;
}

// ---------------- kernel 0b: zero output ----------------
__global__ __launch_bounds__(256) void k_zero_out(float* __restrict__ out) {
    int i = (blockIdx.x * 256 + threadIdx.x) * 4;
    float4 z = make_float4(0.f, 0.f, 0.f, 0.f);
    *(float4*)(out + i) = z;
}

// ---------------- kernel 1: gate (fp32 exact) ----------------
__global__ __launch_bounds__(128) void k_gate(const float* __restrict__ x,
                                              const float* __restrict__ gw) {
    __shared__ float sx[DIM];
    __shared__ float slog[NEXP];
    int t = blockIdx.x;
    const float* xr = x + (size_t)t * DIM;
    for (int i = threadIdx.x * 4; i < DIM; i += 128 * 4)
        *(float4*)(sx + i) = *(const float4*)(xr + i);
    __syncthreads();

    int e = threadIdx.x >> 2, part = threadIdx.x & 3;
    const float* wr = gw + (size_t)e * DIM;
    float s = 0.f;
    for (int k = part * 4; k < DIM; k += 16) {
        float4 a = *(const float4*)(sx + k);
        float4 b = *(const float4*)(wr + k);
        s += a.x * b.x + a.y * b.y + a.z * b.z + a.w * b.w;
    }
    s += __shfl_down_sync(0xffffffffu, s, 2, 4);
    s += __shfl_down_sync(0xffffffffu, s, 1, 4);
    if (part == 0) slog[e] = s;
    __syncthreads();

    if (threadIdx.x < 32) {
        float sc = slog[threadIdx.x];
        float m = sc;
        for (int o = 16; o; o >>= 1) m = fmaxf(m, __shfl_xor_sync(0xffffffffu, m, o));
        float p = expf(sc - m);
        float sum = p;
        for (int o = 16; o; o >>= 1) sum += __shfl_xor_sync(0xffffffffu, sum, o);
        float v = p / sum;
        for (int r = 0; r < TOPK; r++) {
            float mv = v;
            for (int o = 16; o; o >>= 1) mv = fmaxf(mv, __shfl_xor_sync(0xffffffffu, mv, o));
            unsigned bal = __ballot_sync(0xffffffffu, v == mv);
            int idx = __ffs(bal) - 1;
            if (threadIdx.x == 0) {
                g_topi[t * TOPK + r] = idx;
                g_topw[t * TOPK + r] = mv;
                atomicAdd(&g_cnt[idx], 1);
            }
            if (threadIdx.x == idx) v = -1.f;
        }
    }
}

// ---------------- kernel 2: offsets + tile map ----------------
__global__ void k_build() {
    if (threadIdx.x == 0) {
        int off = 0;
        for (int e = 0; e < NEXP; e++) { g_off[e] = off; off += g_cnt[e]; }
        g_off[NEXP] = off;
        int nt = 0;
        for (int e = 0; e < NEXP; e++) {
            int n = g_cnt[e], base = g_off[e];
            for (int r0 = 0; r0 < n; r0 += BM) {
                g_tile_e[nt] = e; g_tile_r0[nt] = base + r0;
                g_tile_n[nt] = min(BM, n - r0); nt++;
            }
        }
        g_ntiles = nt;
    }
}

// ---------------- kernel 3: parallel deterministic scatter ----------------
__global__ __launch_bounds__(256) void k_scatter() {
    int e = blockIdx.x, tid = threadIdx.x, w = tid >> 5, lane = tid & 31;
    __shared__ int wc[8];
    int t0 = w * 256;
    int cnt = 0;
    for (int i = 0; i < 8; i++) {
        int t = t0 + i * 32 + lane;
        bool f = false;
        #pragma unroll
        for (int k = 0; k < TOPK; k++) if (g_topi[t * TOPK + k] == e) f = true;
        cnt += __popc(__ballot_sync(0xffffffffu, f));
    }
    if (lane == 0) wc[w] = cnt;
    __syncthreads();
    int base = g_off[e];
    for (int ww = 0; ww < w; ww++) base += wc[ww];
    for (int i = 0; i < 8; i++) {
        int t = t0 + i * 32 + lane;
        float wt = 0.f; bool f = false;
        #pragma unroll
        for (int k = 0; k < TOPK; k++)
            if (g_topi[t * TOPK + k] == e) { f = true; wt = g_topw[t * TOPK + k]; }
        unsigned bal = __ballot_sync(0xffffffffu, f);
        int pos = base + __popc(bal & ((1u << lane) - 1u));
        if (f) { g_tok[pos] = t; g_wt[pos] = wt; }
        base += __popc(bal);
    }
}

// ---------------- merged up kernel (fp16 mma) ------------------------------
__global__ __launch_bounds__(256, 2) void k_up(const float* __restrict__ x,
                                               const float* __restrict__ w1,
                                               const float* __restrict__ w3,
                                               const float* __restrict__ sw1,
                                               const float* __restrict__ sw3) {
    constexpr int KC = 32;
    constexpr int NCH = DIM / KC;             // 64

    extern __shared__ float sm[];
    __shared__ int s_tok[BM];

    int bid = blockIdx.x;
    int e = 0, r0, nvalid = BM, jblk;
    const float *pw1, *pw3;
    float* dstH; int dstride, ni;
    bool routed = bid < UP_RB;
    if (routed) {
        int tile = bid >> 4;
        if (tile >= g_ntiles) return;
        jblk = (bid & 15) * 64;
        e = g_tile_e[tile]; r0 = g_tile_r0[tile]; nvalid = g_tile_n[tile];
        pw1 = w1; pw3 = w3; dstH = g_h; dstride = INTER; ni = INTER;
    } else {
        int sid = bid - UP_RB;
        int tile = sid >> 5;
        jblk = (sid & 31) * 64;
        r0 = tile * BM;
        pw1 = sw1; pw3 = sw3; dstH = g_hs; dstride = SHIN; ni = SHIN;
    }

    int tid = threadIdx.x, wid = tid >> 5, lane = tid & 31;
    int wm = wid & 3, wn = wid >> 2;          // 4 x 2 warps
    int gq = lane >> 2, cq = lane & 3;

    if (tid < BM)
        s_tok[tid] = routed ? g_tok[r0 + min(tid, nvalid - 1)] : (r0 + tid);
    __syncthreads();

    const float* gp[8];
    uint32_t so[8];
    uint32_t smu = smem_u32(sm);
    #pragma unroll
    for (int j = 0; j < 8; j++) {
        int id = tid + j * 256;
        int r = id >> 3;
        int s = id & 7;
        so[j] = (uint32_t)(r * PADS + s * 4);
        if (r < 128) gp[j] = x + (size_t)s_tok[r] * DIM + s * 4;
        else {
            int rb = r - 128;
            if (rb < 64) gp[j] = pw1 + ((size_t)e * ni + jblk + rb) * DIM + s * 4;
            else         gp[j] = pw3 + ((size_t)e * ni + jblk + (rb - 64)) * DIM + s * 4;
        }
    }

    float acc1[2][4][4], acc3[2][4][4];
    #pragma unroll
    for (int i = 0; i < 2; i++)
        #pragma unroll
        for (int j = 0; j < 4; j++)
            #pragma unroll
            for (int q = 0; q < 4; q++) { acc1[i][j][q] = 0.f; acc3[i][j][q] = 0.f; }

    // ldmatrix lane offset (bytes): rows 0-15 (lane&15), k-half by lane bit 4
    uint32_t laneOff = (uint32_t)((lane & 15) * (PADH * 4) + ((lane & 16) ? 16 : 0));

    #pragma unroll
    for (int j = 0; j < 8; j++) cp16(smu + so[j] * 4, gp[j]);
    CP_COMMIT();
    #pragma unroll
    for (int j = 0; j < 8; j++) cp16(smu + (FWORDS + so[j]) * 4, gp[j] + KC);
    CP_COMMIT();

    for (int c = 0; c < NCH; c++) {
        int st = c & 1;
        cp_wait<1>();
        __syncthreads();

        // convert fp32 stage -> packed fp16 stage
        float* F = sm + st * FWORDS;
        uint32_t* H = (uint32_t*)(sm + HBASE + st * HWORDS);
        #pragma unroll
        for (int j = 0; j < 8; j++) {
            float4 v = *(float4*)(F + so[j]);
            uint32_t r = so[j] >> 5;
            uint32_t s2 = (so[j] & 31) >> 1;
            uint2 w;
            w.x = pk16(v.x, v.y);
            w.y = pk16(v.z, v.w);
            *(uint2*)(H + r * PADH + s2) = w;
        }
        __syncthreads();

        // prefetch chunk c+2 into the fp32 stage just consumed
        if (c + 2 < NCH) {
            int kb = (c + 2) * KC;
            #pragma unroll
            for (int j = 0; j < 8; j++)
                cp16(smu + (st * FWORDS + so[j]) * 4, gp[j] + kb);
        }
        CP_COMMIT();

        uint32_t hA = smu + (HBASE + st * HWORDS) * 4;
        uint32_t hB = hA + 128 * PADH * 4;

        #pragma unroll
        for (int ks = 0; ks < 2; ks++) {
            uint32_t ko = (uint32_t)(ks * 32);
            uint32_t a[2][4];
            #pragma unroll
            for (int i = 0; i < 2; i++)
                ldsm4(a[i], hA + (uint32_t)((wm * 32 + i * 16) * (PADH * 4)) + ko + laneOff);
            uint32_t b1[2][4], b3[2][4];
            #pragma unroll
            for (int j2 = 0; j2 < 2; j2++) {
                int nb = wn * 32 + j2 * 16;
                ldsm4(b1[j2], hB + (uint32_t)(nb * (PADH * 4)) + ko + laneOff);
                ldsm4(b3[j2], hB + (uint32_t)((64 + nb) * (PADH * 4)) + ko + laneOff);
            }
            #pragma unroll
            for (int i = 0; i < 2; i++)
                #pragma unroll
                for (int j2 = 0; j2 < 2; j2++) {
                    mma16(acc1[i][j2 * 2 + 0], a[i], b1[j2][0], b1[j2][2]);
                    mma16(acc1[i][j2 * 2 + 1], a[i], b1[j2][1], b1[j2][3]);
                    mma16(acc3[i][j2 * 2 + 0], a[i], b3[j2][0], b3[j2][2]);
                    mma16(acc3[i][j2 * 2 + 1], a[i], b3[j2][1], b3[j2][3]);
                }
        }
    }

    #pragma unroll
    for (int i = 0; i < 2; i++) {
        int rbase = wm * 32 + i * 16 + gq;
        #pragma unroll
        for (int j = 0; j < 4; j++) {
            int col = jblk + wn * 32 + j * 8 + 2 * cq;
            if (rbase < nvalid) {
                float2 o;
                o.x = silu_f(acc1[i][j][0]) * acc3[i][j][0];
                o.y = silu_f(acc1[i][j][1]) * acc3[i][j][1];
                *(float2*)(dstH + (size_t)(r0 + rbase) * dstride + col) = o;
            }
            if (rbase + 8 < nvalid) {
                float2 o;
                o.x = silu_f(acc1[i][j][2]) * acc3[i][j][2];
                o.y = silu_f(acc1[i][j][3]) * acc3[i][j][3];
                *(float2*)(dstH + (size_t)(r0 + rbase + 8) * dstride + col) = o;
            }
        }
    }
}

// ---------------- merged down kernel (fp16 mma) ----------------------------
__global__ __launch_bounds__(256, 2) void k_down(const float* __restrict__ w2,
                                                 const float* __restrict__ sw2,
                                                 float* __restrict__ out) {
    constexpr int KC = 32;

    extern __shared__ float sm[];
    __shared__ int   s_tok[BM];
    __shared__ float s_wtv[BM];

    int bid = blockIdx.x;
    int e = 0, r0, nvalid = BM, dblk, kd, nch;
    const float* srcH; int sstride;
    const float* pb;
    bool routed = bid < DN_RB;
    if (routed) {
        int tile = bid >> 4;
        if (tile >= g_ntiles) return;
        dblk = (bid & 15) * 128;
        e = g_tile_e[tile]; r0 = g_tile_r0[tile]; nvalid = g_tile_n[tile];
        srcH = g_h; sstride = INTER; kd = INTER; nch = INTER / KC;
        pb = w2;
    } else {
        int sid = bid - DN_RB;
        int tile = sid >> 4;
        dblk = (sid & 15) * 128;
        r0 = tile * BM;
        srcH = g_hs; sstride = SHIN; kd = SHIN; nch = SHIN / KC;
        pb = sw2;
    }

    int tid = threadIdx.x, wid = tid >> 5, lane = tid & 31;
    int wm = wid & 3, wn = wid >> 2;
    int gq = lane >> 2, cq = lane & 3;

    if (tid < BM) {
        if (routed) {
            int ok = tid < nvalid;
            s_tok[tid] = ok ? g_tok[r0 + tid] : 0;
            s_wtv[tid] = ok ? g_wt[r0 + tid]  : 0.f;
        } else { s_tok[tid] = r0 + tid; s_wtv[tid] = 1.f; }
    }
    __syncthreads();

    const float* gp[8];
    uint32_t so[8];
    uint32_t smu = smem_u32(sm);
    #pragma unroll
    for (int j = 0; j < 8; j++) {
        int id = tid + j * 256;
        int r = id >> 3;
        int s = id & 7;
        so[j] = (uint32_t)(r * PADS + s * 4);
        if (r < 128) gp[j] = srcH + (size_t)min(r0 + r, (routed ? NA : TT) - 1) * sstride + s * 4;
        else         gp[j] = pb + ((size_t)e * DIM + dblk + (r - 128)) * kd + s * 4;
    }

    float acc[2][8][4];
    #pragma unroll
    for (int i = 0; i < 2; i++)
        #pragma unroll
        for (int j = 0; j < 8; j++)
            #pragma unroll
            for (int q = 0; q < 4; q++) acc[i][j][q] = 0.f;

    uint32_t laneOff = (uint32_t)((lane & 15) * (PADH * 4) + ((lane & 16) ? 16 : 0));

    #pragma unroll
    for (int j = 0; j < 8; j++) cp16(smu + so[j] * 4, gp[j]);
    CP_COMMIT();
    #pragma unroll
    for (int j = 0; j < 8; j++) cp16(smu + (FWORDS + so[j]) * 4, gp[j] + KC);
    CP_COMMIT();

    for (int c = 0; c < nch; c++) {
        int st = c & 1;
        cp_wait<1>();
        __syncthreads();

        float* F = sm + st * FWORDS;
        uint32_t* H = (uint32_t*)(sm + HBASE + st * HWORDS);
        #pragma unroll
        for (int j = 0; j < 8; j++) {
            float4 v = *(float4*)(F + so[j]);
            uint32_t r = so[j] >> 5;
            uint32_t s2 = (so[j] & 31) >> 1;
            uint2 w;
            w.x = pk16(v.x, v.y);
            w.y = pk16(v.z, v.w);
            *(uint2*)(H + r * PADH + s2) = w;
        }
        __syncthreads();

        if (c + 2 < nch) {
            int kb = (c + 2) * KC;
            #pragma unroll
            for (int j = 0; j < 8; j++)
                cp16(smu + (st * FWORDS + so[j]) * 4, gp[j] + kb);
        }
        CP_COMMIT();

        uint32_t hA = smu + (HBASE + st * HWORDS) * 4;
        uint32_t hB = hA + 128 * PADH * 4;

        #pragma unroll
        for (int ks = 0; ks < 2; ks++) {
            uint32_t ko = (uint32_t)(ks * 32);
            uint32_t a[2][4];
            #pragma unroll
            for (int i = 0; i < 2; i++)
                ldsm4(a[i], hA + (uint32_t)((wm * 32 + i * 16) * (PADH * 4)) + ko + laneOff);
            uint32_t b[4][4];
            #pragma unroll
            for (int j2 = 0; j2 < 4; j2++)
                ldsm4(b[j2], hB + (uint32_t)((wn * 64 + j2 * 16) * (PADH * 4)) + ko + laneOff);
            #pragma unroll
            for (int i = 0; i < 2; i++)
                #pragma unroll
                for (int j2 = 0; j2 < 4; j2++) {
                    mma16(acc[i][j2 * 2 + 0], a[i], b[j2][0], b[j2][2]);
                    mma16(acc[i][j2 * 2 + 1], a[i], b[j2][1], b[j2][3]);
                }
        }
    }

    #pragma unroll
    for (int i = 0; i < 2; i++) {
        int rbase = wm * 32 + i * 16 + gq;
        #pragma unroll
        for (int j = 0; j < 8; j++) {
            int col = dblk + wn * 64 + j * 8 + 2 * cq;
            #pragma unroll
            for (int half = 0; half < 2; half++) {
                int r = rbase + half * 8;
                if (r >= nvalid) continue;
                int tok = s_tok[r];
                float wt = s_wtv[r];
                float* dst = out + (size_t)tok * DIM + col;
                atomicAdd(dst + 0, acc[i][j][half * 2 + 0] * wt);
                atomicAdd(dst + 1, acc[i][j][half * 2 + 1] * wt);
            }
        }
    }
}

// ---------------- launch ----------------
extern "C" void kernel_launch(void* const* d_in, const int* in_sizes, int n_in,
                              void* d_out, int out_size) {
    const float* x   = (const float*)d_in[0];
    const float* gw  = (const float*)d_in[1];
    const float* w1  = (const float*)d_in[2];
    const float* w2  = (const float*)d_in[3];
    const float* w3  = (const float*)d_in[4];
    const float* sw1 = (const float*)d_in[5];
    const float* sw2 = (const float*)d_in[6];
    const float* sw3 = (const float*)d_in[7];
    float* out = (float*)d_out;

    const int smBytes = (2 * FWORDS + 2 * HWORDS) * 4;   // 106496
    cudaFuncSetAttribute((const void*)k_up,   cudaFuncAttributeMaxDynamicSharedMemorySize, smBytes);
    cudaFuncSetAttribute((const void*)k_down, cudaFuncAttributeMaxDynamicSharedMemorySize, smBytes);

    k_zero<<<1, 32>>>();
    k_zero_out<<<(TT * DIM) / 1024, 256>>>(out);
    k_gate<<<TT, 128>>>(x, gw);
    k_build<<<1, 1>>>();
    k_scatter<<<NEXP, 256>>>();

    k_up<<<UP_RB + UP_SB, 256, smBytes>>>(x, w1, w3, sw1, sw3);
    k_down<<<DN_RB + DN_SB, 256, smBytes>>>(w2, sw2, out);
}

// round 9
// speedup vs baseline: 1.6990x; 1.0277x over previous
#include <cuda_runtime.h>
#include <cuda_fp16.h>
#include <math.h>
#include <stdint.h>

#define TT 2048
#define DIM 2048
#define NEXP 32
#define TOPK 4
#define INTER 1024
#define SHIN 2048
#define NA (TT*TOPK)
#define BM 128
#define MAXTILES (NA/BM + NEXP)   /* 96 */

#define KC 64                     /* K halfs per chunk */
#define RW 36                     /* words per fp16 stage row (32 data + 4 pad) */
#define STGW (256*RW)             /* 9216 words per stage */

#define UP_RB   (MAXTILES * 16)
#define UP_SB   (16 * 32)
#define DN_RB   (MAXTILES * 16)
#define DN_SB   (16 * 16)

// ---------------- device scratch ----------------
__device__ int   g_topi[TT*TOPK];
__device__ float g_topw[TT*TOPK];
__device__ int   g_cnt[NEXP];
__device__ int   g_off[NEXP+1];
__device__ int   g_tok[NA];
__device__ float g_wt[NA];
__device__ int   g_tile_e[MAXTILES];
__device__ int   g_tile_r0[MAXTILES];
__device__ int   g_tile_n[MAXTILES];
__device__ int   g_ntiles;

// fp16 copies (converted once per call)
__device__ __half h_w1[(size_t)NEXP*INTER*DIM];
__device__ __half h_w2[(size_t)NEXP*DIM*INTER];
__device__ __half h_w3[(size_t)NEXP*INTER*DIM];
__device__ __half h_sw1[(size_t)SHIN*DIM];
__device__ __half h_sw2[(size_t)DIM*SHIN];
__device__ __half h_sw3[(size_t)SHIN*DIM];
__device__ __half h_x[(size_t)TT*DIM];
__device__ __half h_h[(size_t)NA*INTER];
__device__ __half h_hs[(size_t)TT*SHIN];

// ---------------- helpers ----------------
__device__ __forceinline__ uint32_t smem_u32(const void* p) {
    uint32_t a;
    asm("{ .reg .u64 t; cvta.to.shared.u64 t, %1; cvt.u32.u64 %0, t; }" : "=r"(a) : "l"(p));
    return a;
}
__device__ __forceinline__ uint32_t pk16(float lo, float hi) {
    uint32_t r; asm("cvt.rn.f16x2.f32 %0, %1, %2;" : "=r"(r) : "f"(hi), "f"(lo)); return r;
}
__device__ __forceinline__ void cp16(uint32_t dst, const void* src) {
    asm volatile("cp.async.cg.shared.global [%0], [%1], 16;" :: "r"(dst), "l"(src));
}
#define CP_COMMIT() asm volatile("cp.async.commit_group;" ::: "memory")
template<int N>
__device__ __forceinline__ void cp_wait() {
    asm volatile("cp.async.wait_group %0;" :: "n"(N) : "memory");
}
__device__ __forceinline__ void mma16(float* c, const uint32_t* a, uint32_t b0, uint32_t b1) {
    asm volatile("mma.sync.aligned.m16n8k16.row.col.f32.f16.f16.f32 "
        "{%0,%1,%2,%3}, {%4,%5,%6,%7}, {%8,%9}, {%0,%1,%2,%3};"
        : "+f"(c[0]), "+f"(c[1]), "+f"(c[2]), "+f"(c[3])
        : "r"(a[0]), "r"(a[1]), "r"(a[2]), "r"(a[3]), "r"(b0), "r"(b1));
}
__device__ __forceinline__ void ldsm4(uint32_t* r, uint32_t addr) {
    asm volatile("ldmatrix.sync.aligned.m8n8.x4.shared.b16 {%0,%1,%2,%3}, [%4];"
        : "=r"(r[0]), "=r"(r[1]), "=r"(r[2]), "=r"(r[3]) : "r"(addr));
}
__device__ __forceinline__ float silu_f(float v) { return v / (1.0f + __expf(-v)); }

// ---------------- fp32 -> fp16 convert (streaming) ----------------
__global__ __launch_bounds__(256) void k_f2h(const float4* __restrict__ src,
                                             uint2* __restrict__ dst, int n4) {
    int i = blockIdx.x * 256 + threadIdx.x;
    if (i < n4) {
        float4 v = src[i];
        uint2 w;
        w.x = pk16(v.x, v.y);
        w.y = pk16(v.z, v.w);
        dst[i] = w;
    }
}

// ---------------- kernel 0: zero counters ----------------
__global__ void k_zero() {
    if (threadIdx.x < NEXP) g_cnt[threadIdx.x] = 0;
}

// ---------------- kernel 0b: zero output ----------------
__global__ __launch_bounds__(256) void k_zero_out(float* __restrict__ out) {
    int i = (blockIdx.x * 256 + threadIdx.x) * 4;
    float4 z = make_float4(0.f, 0.f, 0.f, 0.f);
    *(float4*)(out + i) = z;
}

// ---------------- kernel 1: gate (fp32 exact) ----------------
__global__ __launch_bounds__(128) void k_gate(const float* __restrict__ x,
                                              const float* __restrict__ gw) {
    __shared__ float sx[DIM];
    __shared__ float slog[NEXP];
    int t = blockIdx.x;
    const float* xr = x + (size_t)t * DIM;
    for (int i = threadIdx.x * 4; i < DIM; i += 128 * 4)
        *(float4*)(sx + i) = *(const float4*)(xr + i);
    __syncthreads();

    int e = threadIdx.x >> 2, part = threadIdx.x & 3;
    const float* wr = gw + (size_t)e * DIM;
    float s = 0.f;
    for (int k = part * 4; k < DIM; k += 16) {
        float4 a = *(const float4*)(sx + k);
        float4 b = *(const float4*)(wr + k);
        s += a.x * b.x + a.y * b.y + a.z * b.z + a.w * b.w;
    }
    s += __shfl_down_sync(0xffffffffu, s, 2, 4);
    s += __shfl_down_sync(0xffffffffu, s, 1, 4);
    if (part == 0) slog[e] = s;
    __syncthreads();

    if (threadIdx.x < 32) {
        float sc = slog[threadIdx.x];
        float m = sc;
        for (int o = 16; o; o >>= 1) m = fmaxf(m, __shfl_xor_sync(0xffffffffu, m, o));
        float p = expf(sc - m);
        float sum = p;
        for (int o = 16; o; o >>= 1) sum += __shfl_xor_sync(0xffffffffu, sum, o);
        float v = p / sum;
        for (int r = 0; r < TOPK; r++) {
            float mv = v;
            for (int o = 16; o; o >>= 1) mv = fmaxf(mv, __shfl_xor_sync(0xffffffffu, mv, o));
            unsigned bal = __ballot_sync(0xffffffffu, v == mv);
            int idx = __ffs(bal) - 1;
            if (threadIdx.x == 0) {
                g_topi[t * TOPK + r] = idx;
                g_topw[t * TOPK + r] = mv;
                atomicAdd(&g_cnt[idx], 1);
            }
            if (threadIdx.x == idx) v = -1.f;
        }
    }
}

// ---------------- kernel 2: offsets + tile map (1 warp, parallel) ---------
__global__ __launch_bounds__(32) void k_build() {
    int lane = threadIdx.x;
    int n = g_cnt[lane];
    int off = n;
    #pragma unroll
    for (int o = 1; o < 32; o <<= 1) {
        int v = __shfl_up_sync(0xffffffffu, off, o);
        if (lane >= o) off += v;
    }
    int excl = off - n;
    g_off[lane] = excl;
    if (lane == 31) g_off[NEXP] = off;

    int nt = (n + BM - 1) / BM;
    int tb = nt;
    #pragma unroll
    for (int o = 1; o < 32; o <<= 1) {
        int v = __shfl_up_sync(0xffffffffu, tb, o);
        if (lane >= o) tb += v;
    }
    int texcl = tb - nt;
    if (lane == 31) g_ntiles = tb;
    for (int t = 0; t < nt; t++) {
        g_tile_e[texcl + t]  = lane;
        g_tile_r0[texcl + t] = excl + t * BM;
        g_tile_n[texcl + t]  = min(BM, n - t * BM);
    }
}

// ---------------- kernel 3: parallel deterministic scatter ----------------
__global__ __launch_bounds__(256) void k_scatter() {
    int e = blockIdx.x, tid = threadIdx.x, w = tid >> 5, lane = tid & 31;
    __shared__ int wc[8];
    int t0 = w * 256;
    int cnt = 0;
    for (int i = 0; i < 8; i++) {
        int t = t0 + i * 32 + lane;
        bool f = false;
        #pragma unroll
        for (int k = 0; k < TOPK; k++) if (g_topi[t * TOPK + k] == e) f = true;
        cnt += __popc(__ballot_sync(0xffffffffu, f));
    }
    if (lane == 0) wc[w] = cnt;
    __syncthreads();
    int base = g_off[e];
    for (int ww = 0; ww < w; ww++) base += wc[ww];
    for (int i = 0; i < 8; i++) {
        int t = t0 + i * 32 + lane;
        float wt = 0.f; bool f = false;
        #pragma unroll
        for (int k = 0; k < TOPK; k++)
            if (g_topi[t * TOPK + k] == e) { f = true; wt = g_topw[t * TOPK + k]; }
        unsigned bal = __ballot_sync(0xffffffffu, f);
        int pos = base + __popc(bal & ((1u << lane) - 1u));
        if (f) { g_tok[pos] = t; g_wt[pos] = wt; }
        base += __popc(bal);
    }
}

// ---------------- merged up kernel (fp16 operands, fp16 mma) --------------
__global__ __launch_bounds__(256, 2) void k_up() {
    constexpr int NCH = DIM / KC;             // 32

    extern __shared__ uint32_t sm[];
    __shared__ int s_tok[BM];

    int bid = blockIdx.x;
    int e = 0, r0, nvalid = BM, jblk;
    const __half *pw1, *pw3;
    __half* dstH; int dstride, ni;
    bool routed = bid < UP_RB;
    if (routed) {
        int tile = bid >> 4;
        if (tile >= g_ntiles) return;
        jblk = (bid & 15) * 64;
        e = g_tile_e[tile]; r0 = g_tile_r0[tile]; nvalid = g_tile_n[tile];
        pw1 = h_w1; pw3 = h_w3; dstH = h_h; dstride = INTER; ni = INTER;
    } else {
        int sid = bid - UP_RB;
        int tile = sid >> 5;
        jblk = (sid & 31) * 64;
        r0 = tile * BM;
        pw1 = h_sw1; pw3 = h_sw3; dstH = h_hs; dstride = SHIN; ni = SHIN;
    }

    int tid = threadIdx.x, wid = tid >> 5, lane = tid & 31;
    int wm = wid & 3, wn = wid >> 2;          // 4 x 2 warps
    int gq = lane >> 2, cq = lane & 3;

    if (tid < BM)
        s_tok[tid] = routed ? g_tok[r0 + min(tid, nvalid - 1)] : (r0 + tid);
    __syncthreads();

    // loader: 8 x 16B (8 halfs) segments per thread per chunk
    const __half* gp[8];
    uint32_t so[8];
    uint32_t smu = smem_u32(sm);
    #pragma unroll
    for (int j = 0; j < 8; j++) {
        int id = tid + j * 256;               // 0..2047
        int r = id >> 3;                      // 0..255
        int s = id & 7;
        so[j] = (uint32_t)(r * RW + s * 4);
        if (r < 128) gp[j] = h_x + (size_t)s_tok[r] * DIM + s * 8;
        else {
            int rb = r - 128;
            if (rb < 64) gp[j] = pw1 + ((size_t)e * ni + jblk + rb) * DIM + s * 8;
            else         gp[j] = pw3 + ((size_t)e * ni + jblk + (rb - 64)) * DIM + s * 8;
        }
    }

    float acc1[2][4][4], acc3[2][4][4];
    #pragma unroll
    for (int i = 0; i < 2; i++)
        #pragma unroll
        for (int j = 0; j < 4; j++)
            #pragma unroll
            for (int q = 0; q < 4; q++) { acc1[i][j][q] = 0.f; acc3[i][j][q] = 0.f; }

    uint32_t laneOff = (uint32_t)((lane & 15) * (RW * 4) + ((lane & 16) ? 16 : 0));

    #pragma unroll
    for (int j = 0; j < 8; j++) cp16(smu + so[j] * 4, gp[j]);
    CP_COMMIT();
    #pragma unroll
    for (int j = 0; j < 8; j++) cp16(smu + (STGW + so[j]) * 4, gp[j] + KC);
    CP_COMMIT();

    for (int c = 0; c < NCH; c++) {
        int st = c % 3;
        cp_wait<1>();
        __syncthreads();

        uint32_t hA = smu + (uint32_t)(st * STGW) * 4;
        uint32_t hB = hA + 128 * RW * 4;

        #pragma unroll
        for (int ks = 0; ks < 4; ks++) {
            uint32_t ko = (uint32_t)(ks * 32);
            uint32_t a[2][4];
            #pragma unroll
            for (int i = 0; i < 2; i++)
                ldsm4(a[i], hA + (uint32_t)((wm * 32 + i * 16) * (RW * 4)) + ko + laneOff);
            uint32_t b1[2][4], b3[2][4];
            #pragma unroll
            for (int j2 = 0; j2 < 2; j2++) {
                int nb = wn * 32 + j2 * 16;
                ldsm4(b1[j2], hB + (uint32_t)(nb * (RW * 4)) + ko + laneOff);
                ldsm4(b3[j2], hB + (uint32_t)((64 + nb) * (RW * 4)) + ko + laneOff);
            }
            #pragma unroll
            for (int i = 0; i < 2; i++)
                #pragma unroll
                for (int j2 = 0; j2 < 2; j2++) {
                    mma16(acc1[i][j2 * 2 + 0], a[i], b1[j2][0], b1[j2][2]);
                    mma16(acc1[i][j2 * 2 + 1], a[i], b1[j2][1], b1[j2][3]);
                    mma16(acc3[i][j2 * 2 + 0], a[i], b3[j2][0], b3[j2][2]);
                    mma16(acc3[i][j2 * 2 + 1], a[i], b3[j2][1], b3[j2][3]);
                }
        }

        if (c + 2 < NCH) {
            int st2 = (c + 2) % 3;
            int kb = (c + 2) * KC;
            #pragma unroll
            for (int j = 0; j < 8; j++)
                cp16(smu + (st2 * STGW + so[j]) * 4, gp[j] + kb);
        }
        CP_COMMIT();
    }

    #pragma unroll
    for (int i = 0; i < 2; i++) {
        int rbase = wm * 32 + i * 16 + gq;
        #pragma unroll
        for (int j = 0; j < 4; j++) {
            int col = jblk + wn * 32 + j * 8 + 2 * cq;
            if (rbase < nvalid) {
                uint32_t o = pk16(silu_f(acc1[i][j][0]) * acc3[i][j][0],
                                  silu_f(acc1[i][j][1]) * acc3[i][j][1]);
                *(uint32_t*)(dstH + (size_t)(r0 + rbase) * dstride + col) = o;
            }
            if (rbase + 8 < nvalid) {
                uint32_t o = pk16(silu_f(acc1[i][j][2]) * acc3[i][j][2],
                                  silu_f(acc1[i][j][3]) * acc3[i][j][3]);
                *(uint32_t*)(dstH + (size_t)(r0 + rbase + 8) * dstride + col) = o;
            }
        }
    }
}

// ---------------- merged down kernel (fp16 operands, fp16 mma) ------------
__global__ __launch_bounds__(256, 2) void k_down(float* __restrict__ out) {
    extern __shared__ uint32_t sm[];
    __shared__ int   s_tok[BM];
    __shared__ float s_wtv[BM];

    int bid = blockIdx.x;
    int e = 0, r0, nvalid = BM, dblk, kd, nch;
    const __half* srcH; int sstride;
    const __half* pb;
    bool routed = bid < DN_RB;
    if (routed) {
        int tile = bid >> 4;
        if (tile >= g_ntiles) return;
        dblk = (bid & 15) * 128;
        e = g_tile_e[tile]; r0 = g_tile_r0[tile]; nvalid = g_tile_n[tile];
        srcH = h_h; sstride = INTER; kd = INTER; nch = INTER / KC;     // 16
        pb = h_w2;
    } else {
        int sid = bid - DN_RB;
        int tile = sid >> 4;
        dblk = (sid & 15) * 128;
        r0 = tile * BM;
        srcH = h_hs; sstride = SHIN; kd = SHIN; nch = SHIN / KC;       // 32
        pb = h_sw2;
    }

    int tid = threadIdx.x, wid = tid >> 5, lane = tid & 31;
    int wm = wid & 3, wn = wid >> 2;
    int gq = lane >> 2, cq = lane & 3;

    if (tid < BM) {
        if (routed) {
            int ok = tid < nvalid;
            s_tok[tid] = ok ? g_tok[r0 + tid] : 0;
            s_wtv[tid] = ok ? g_wt[r0 + tid]  : 0.f;
        } else { s_tok[tid] = r0 + tid; s_wtv[tid] = 1.f; }
    }
    __syncthreads();

    const __half* gp[8];
    uint32_t so[8];
    uint32_t smu = smem_u32(sm);
    #pragma unroll
    for (int j = 0; j < 8; j++) {
        int id = tid + j * 256;
        int r = id >> 3;
        int s = id & 7;
        so[j] = (uint32_t)(r * RW + s * 4);
        if (r < 128) gp[j] = srcH + (size_t)min(r0 + r, (routed ? NA : TT) - 1) * sstride + s * 8;
        else         gp[j] = pb + ((size_t)e * DIM + dblk + (r - 128)) * kd + s * 8;
    }

    float acc[2][8][4];
    #pragma unroll
    for (int i = 0; i < 2; i++)
        #pragma unroll
        for (int j = 0; j < 8; j++)
            #pragma unroll
            for (int q = 0; q < 4; q++) acc[i][j][q] = 0.f;

    uint32_t laneOff = (uint32_t)((lane & 15) * (RW * 4) + ((lane & 16) ? 16 : 0));

    #pragma unroll
    for (int j = 0; j < 8; j++) cp16(smu + so[j] * 4, gp[j]);
    CP_COMMIT();
    #pragma unroll
    for (int j = 0; j < 8; j++) cp16(smu + (STGW + so[j]) * 4, gp[j] + KC);
    CP_COMMIT();

    for (int c = 0; c < nch; c++) {
        int st = c % 3;
        cp_wait<1>();
        __syncthreads();

        uint32_t hA = smu + (uint32_t)(st * STGW) * 4;
        uint32_t hB = hA + 128 * RW * 4;

        #pragma unroll
        for (int ks = 0; ks < 4; ks++) {
            uint32_t ko = (uint32_t)(ks * 32);
            uint32_t a[2][4];
            #pragma unroll
            for (int i = 0; i < 2; i++)
                ldsm4(a[i], hA + (uint32_t)((wm * 32 + i * 16) * (RW * 4)) + ko + laneOff);
            uint32_t b[4][4];
            #pragma unroll
            for (int j2 = 0; j2 < 4; j2++)
                ldsm4(b[j2], hB + (uint32_t)((wn * 64 + j2 * 16) * (RW * 4)) + ko + laneOff);
            #pragma unroll
            for (int i = 0; i < 2; i++)
                #pragma unroll
                for (int j2 = 0; j2 < 4; j2++) {
                    mma16(acc[i][j2 * 2 + 0], a[i], b[j2][0], b[j2][2]);
                    mma16(acc[i][j2 * 2 + 1], a[i], b[j2][1], b[j2][3]);
                }
        }

        if (c + 2 < nch) {
            int st2 = (c + 2) % 3;
            int kb = (c + 2) * KC;
            #pragma unroll
            for (int j = 0; j < 8; j++)
                cp16(smu + (st2 * STGW + so[j]) * 4, gp[j] + kb);
        }
        CP_COMMIT();
    }

    #pragma unroll
    for (int i = 0; i < 2; i++) {
        int rbase = wm * 32 + i * 16 + gq;
        #pragma unroll
        for (int j = 0; j < 8; j++) {
            int col = dblk + wn * 64 + j * 8 + 2 * cq;
            #pragma unroll
            for (int half = 0; half < 2; half++) {
                int r = rbase + half * 8;
                if (r >= nvalid) continue;
                int tok = s_tok[r];
                float wt = s_wtv[r];
                float* dst = out + (size_t)tok * DIM + col;
                atomicAdd(dst + 0, acc[i][j][half * 2 + 0] * wt);
                atomicAdd(dst + 1, acc[i][j][half * 2 + 1] * wt);
            }
        }
    }
}

// ---------------- launch ----------------
extern "C" void kernel_launch(void* const* d_in, const int* in_sizes, int n_in,
                              void* d_out, int out_size) {
    const float* x   = (const float*)d_in[0];
    const float* gw  = (const float*)d_in[1];
    const float* w1  = (const float*)d_in[2];
    const float* w2  = (const float*)d_in[3];
    const float* w3  = (const float*)d_in[4];
    const float* sw1 = (const float*)d_in[5];
    const float* sw2 = (const float*)d_in[6];
    const float* sw3 = (const float*)d_in[7];
    float* out = (float*)d_out;

    void *p_w1, *p_w2, *p_w3, *p_sw1, *p_sw2, *p_sw3, *p_x;
    cudaGetSymbolAddress(&p_w1,  h_w1);
    cudaGetSymbolAddress(&p_w2,  h_w2);
    cudaGetSymbolAddress(&p_w3,  h_w3);
    cudaGetSymbolAddress(&p_sw1, h_sw1);
    cudaGetSymbolAddress(&p_sw2, h_sw2);
    cudaGetSymbolAddress(&p_sw3, h_sw3);
    cudaGetSymbolAddress(&p_x,   h_x);

    const int smBytes = 3 * STGW * 4;   // 110592
    cudaFuncSetAttribute((const void*)k_up,   cudaFuncAttributeMaxDynamicSharedMemorySize, smBytes);
    cudaFuncSetAttribute((const void*)k_down, cudaFuncAttributeMaxDynamicSharedMemorySize, smBytes);

    // convert weights + x to fp16
    const int NW = NEXP * INTER * DIM / 4;   // 16.78M float4 groups
    const int NS = SHIN * DIM / 4;           // 1.05M
    k_f2h<<<NW / 256, 256>>>((const float4*)w1,  (uint2*)p_w1,  NW);
    k_f2h<<<NW / 256, 256>>>((const float4*)w2,  (uint2*)p_w2,  NW);
    k_f2h<<<NW / 256, 256>>>((const float4*)w3,  (uint2*)p_w3,  NW);
    k_f2h<<<NS / 256, 256>>>((const float4*)sw1, (uint2*)p_sw1, NS);
    k_f2h<<<NS / 256, 256>>>((const float4*)sw2, (uint2*)p_sw2, NS);
    k_f2h<<<NS / 256, 256>>>((const float4*)sw3, (uint2*)p_sw3, NS);
    k_f2h<<<NS / 256, 256>>>((const float4*)x,   (uint2*)p_x,   NS);

    k_zero<<<1, 32>>>();
    k_zero_out<<<(TT * DIM) / 1024, 256>>>(out);
    k_gate<<<TT, 128>>>(x, gw);
    k_build<<<1, 32>>>();
    k_scatter<<<NEXP, 256>>>();

    k_up<<<UP_RB + UP_SB, 256, smBytes>>>();
    k_down<<<DN_RB + DN_SB, 256, smBytes>>>(out);
}

// round 10
// speedup vs baseline: 1.7310x; 1.0188x over previous
#include <cuda_runtime.h>
#include <cuda_fp16.h>
#include <math.h>
#include <stdint.h>

#define TT 2048
#define DIM 2048
#define NEXP 32
#define TOPK 4
#define INTER 1024
#define SHIN 2048
#define NA (TT*TOPK)
#define BM 128
#define MAXTILES (NA/BM + NEXP)   /* 96 */

#define KC 64                     /* K halfs per chunk */
#define RW 36                     /* words per fp16 stage row (32 data + 4 pad) */
#define STGW (256*RW)             /* 9216 words per stage */

#define UP_RB   (MAXTILES * 16)
#define UP_SB   (16 * 32)
#define DN_RB   (MAXTILES * 16)
#define DN_SB   (16 * 16)

// ---------------- device scratch ----------------
__device__ int   g_topi[TT*TOPK];
__device__ float g_topw[TT*TOPK];
__device__ int   g_cnt[NEXP];
__device__ int   g_off[NEXP+1];
__device__ int   g_tok[NA];
__device__ float g_wt[NA];
__device__ int   g_tile_e[MAXTILES];
__device__ int   g_tile_r0[MAXTILES];
__device__ int   g_tile_n[MAXTILES];
__device__ int   g_ntiles;

// fp16 copies (converted once per call)
__device__ __half h_w1[(size_t)NEXP*INTER*DIM];
__device__ __half h_w2[(size_t)NEXP*DIM*INTER];
__device__ __half h_w3[(size_t)NEXP*INTER*DIM];
__device__ __half h_sw1[(size_t)SHIN*DIM];
__device__ __half h_sw2[(size_t)DIM*SHIN];
__device__ __half h_sw3[(size_t)SHIN*DIM];
__device__ __half h_x[(size_t)TT*DIM];
__device__ __half h_h[(size_t)NA*INTER];
__device__ __half h_hs[(size_t)TT*SHIN];

// ---------------- helpers ----------------
__device__ __forceinline__ uint32_t smem_u32(const void* p) {
    uint32_t a;
    asm("{ .reg .u64 t; cvta.to.shared.u64 t, %1; cvt.u32.u64 %0, t; }" : "=r"(a) : "l"(p));
    return a;
}
__device__ __forceinline__ uint32_t pk16(float lo, float hi) {
    uint32_t r; asm("cvt.rn.f16x2.f32 %0, %1, %2;" : "=r"(r) : "f"(hi), "f"(lo)); return r;
}
__device__ __forceinline__ void cp16(uint32_t dst, const void* src) {
    asm volatile("cp.async.cg.shared.global [%0], [%1], 16;" :: "r"(dst), "l"(src));
}
#define CP_COMMIT() asm volatile("cp.async.commit_group;" ::: "memory")
template<int N>
__device__ __forceinline__ void cp_wait() {
    asm volatile("cp.async.wait_group %0;" :: "n"(N) : "memory");
}
__device__ __forceinline__ void mma16(float* c, const uint32_t* a, uint32_t b0, uint32_t b1) {
    asm volatile("mma.sync.aligned.m16n8k16.row.col.f32.f16.f16.f32 "
        "{%0,%1,%2,%3}, {%4,%5,%6,%7}, {%8,%9}, {%0,%1,%2,%3};"
        : "+f"(c[0]), "+f"(c[1]), "+f"(c[2]), "+f"(c[3])
        : "r"(a[0]), "r"(a[1]), "r"(a[2]), "r"(a[3]), "r"(b0), "r"(b1));
}
__device__ __forceinline__ void ldsm4(uint32_t* r, uint32_t addr) {
    asm volatile("ldmatrix.sync.aligned.m8n8.x4.shared.b16 {%0,%1,%2,%3}, [%4];"
        : "=r"(r[0]), "=r"(r[1]), "=r"(r[2]), "=r"(r[3]) : "r"(addr));
}
__device__ __forceinline__ float silu_f(float v) { return v / (1.0f + __expf(-v)); }

// ---------------- fp32 -> fp16 convert, ILP=4, streaming ----------------
__global__ __launch_bounds__(256) void k_f2h(const float4* __restrict__ src,
                                             uint2* __restrict__ dst, int n4) {
    int base = blockIdx.x * 1024 + threadIdx.x;
    int i0 = base, i1 = base + 256, i2 = base + 512, i3 = base + 768;
    if (i3 < n4) {
        float4 v0 = __ldcs(src + i0);
        float4 v1 = __ldcs(src + i1);
        float4 v2 = __ldcs(src + i2);
        float4 v3 = __ldcs(src + i3);
        uint2 w0, w1, w2, w3;
        w0.x = pk16(v0.x, v0.y); w0.y = pk16(v0.z, v0.w);
        w1.x = pk16(v1.x, v1.y); w1.y = pk16(v1.z, v1.w);
        w2.x = pk16(v2.x, v2.y); w2.y = pk16(v2.z, v2.w);
        w3.x = pk16(v3.x, v3.y); w3.y = pk16(v3.z, v3.w);
        __stcs(dst + i0, w0);
        __stcs(dst + i1, w1);
        __stcs(dst + i2, w2);
        __stcs(dst + i3, w3);
    } else {
        for (int i = i0; i < n4; i += 256) {
            float4 v = __ldcs(src + i);
            uint2 w;
            w.x = pk16(v.x, v.y); w.y = pk16(v.z, v.w);
            __stcs(dst + i, w);
        }
    }
}

// ---------------- kernel 0: zero counters ----------------
__global__ void k_zero() {
    if (threadIdx.x < NEXP) g_cnt[threadIdx.x] = 0;
}

// ---------------- kernel 0b: zero output ----------------
__global__ __launch_bounds__(256) void k_zero_out(float* __restrict__ out) {
    int i = (blockIdx.x * 256 + threadIdx.x) * 4;
    float4 z = make_float4(0.f, 0.f, 0.f, 0.f);
    *(float4*)(out + i) = z;
}

// ---------------- kernel 1: gate (fp32 exact) ----------------
__global__ __launch_bounds__(128) void k_gate(const float* __restrict__ x,
                                              const float* __restrict__ gw) {
    __shared__ float sx[DIM];
    __shared__ float slog[NEXP];
    int t = blockIdx.x;
    const float* xr = x + (size_t)t * DIM;
    for (int i = threadIdx.x * 4; i < DIM; i += 128 * 4)
        *(float4*)(sx + i) = *(const float4*)(xr + i);
    __syncthreads();

    int e = threadIdx.x >> 2, part = threadIdx.x & 3;
    const float* wr = gw + (size_t)e * DIM;
    float s = 0.f;
    for (int k = part * 4; k < DIM; k += 16) {
        float4 a = *(const float4*)(sx + k);
        float4 b = *(const float4*)(wr + k);
        s += a.x * b.x + a.y * b.y + a.z * b.z + a.w * b.w;
    }
    s += __shfl_down_sync(0xffffffffu, s, 2, 4);
    s += __shfl_down_sync(0xffffffffu, s, 1, 4);
    if (part == 0) slog[e] = s;
    __syncthreads();

    if (threadIdx.x < 32) {
        float sc = slog[threadIdx.x];
        float m = sc;
        for (int o = 16; o; o >>= 1) m = fmaxf(m, __shfl_xor_sync(0xffffffffu, m, o));
        float p = expf(sc - m);
        float sum = p;
        for (int o = 16; o; o >>= 1) sum += __shfl_xor_sync(0xffffffffu, sum, o);
        float v = p / sum;
        for (int r = 0; r < TOPK; r++) {
            float mv = v;
            for (int o = 16; o; o >>= 1) mv = fmaxf(mv, __shfl_xor_sync(0xffffffffu, mv, o));
            unsigned bal = __ballot_sync(0xffffffffu, v == mv);
            int idx = __ffs(bal) - 1;
            if (threadIdx.x == 0) {
                g_topi[t * TOPK + r] = idx;
                g_topw[t * TOPK + r] = mv;
                atomicAdd(&g_cnt[idx], 1);
            }
            if (threadIdx.x == idx) v = -1.f;
        }
    }
}

// ---------------- kernel 2: offsets + tile map (1 warp, parallel) ---------
__global__ __launch_bounds__(32) void k_build() {
    int lane = threadIdx.x;
    int n = g_cnt[lane];
    int off = n;
    #pragma unroll
    for (int o = 1; o < 32; o <<= 1) {
        int v = __shfl_up_sync(0xffffffffu, off, o);
        if (lane >= o) off += v;
    }
    int excl = off - n;
    g_off[lane] = excl;
    if (lane == 31) g_off[NEXP] = off;

    int nt = (n + BM - 1) / BM;
    int tb = nt;
    #pragma unroll
    for (int o = 1; o < 32; o <<= 1) {
        int v = __shfl_up_sync(0xffffffffu, tb, o);
        if (lane >= o) tb += v;
    }
    int texcl = tb - nt;
    if (lane == 31) g_ntiles = tb;
    for (int t = 0; t < nt; t++) {
        g_tile_e[texcl + t]  = lane;
        g_tile_r0[texcl + t] = excl + t * BM;
        g_tile_n[texcl + t]  = min(BM, n - t * BM);
    }
}

// ---------------- kernel 3: parallel deterministic scatter ----------------
__global__ __launch_bounds__(256) void k_scatter() {
    int e = blockIdx.x, tid = threadIdx.x, w = tid >> 5, lane = tid & 31;
    __shared__ int wc[8];
    int t0 = w * 256;
    int cnt = 0;
    for (int i = 0; i < 8; i++) {
        int t = t0 + i * 32 + lane;
        bool f = false;
        #pragma unroll
        for (int k = 0; k < TOPK; k++) if (g_topi[t * TOPK + k] == e) f = true;
        cnt += __popc(__ballot_sync(0xffffffffu, f));
    }
    if (lane == 0) wc[w] = cnt;
    __syncthreads();
    int base = g_off[e];
    for (int ww = 0; ww < w; ww++) base += wc[ww];
    for (int i = 0; i < 8; i++) {
        int t = t0 + i * 32 + lane;
        float wt = 0.f; bool f = false;
        #pragma unroll
        for (int k = 0; k < TOPK; k++)
            if (g_topi[t * TOPK + k] == e) { f = true; wt = g_topw[t * TOPK + k]; }
        unsigned bal = __ballot_sync(0xffffffffu, f);
        int pos = base + __popc(bal & ((1u << lane) - 1u));
        if (f) { g_tok[pos] = t; g_wt[pos] = wt; }
        base += __popc(bal);
    }
}

// ---------------- merged up kernel (fp16 operands, fp16 mma) --------------
__global__ __launch_bounds__(256, 2) void k_up() {
    constexpr int NCH = DIM / KC;             // 32

    extern __shared__ uint32_t sm[];
    __shared__ int s_tok[BM];

    int bid = blockIdx.x;
    int e = 0, r0, nvalid = BM, jblk;
    const __half *pw1, *pw3;
    __half* dstH; int dstride, ni;
    bool routed = bid < UP_RB;
    if (routed) {
        int tile = bid >> 4;
        if (tile >= g_ntiles) return;
        jblk = (bid & 15) * 64;
        e = g_tile_e[tile]; r0 = g_tile_r0[tile]; nvalid = g_tile_n[tile];
        pw1 = h_w1; pw3 = h_w3; dstH = h_h; dstride = INTER; ni = INTER;
    } else {
        int sid = bid - UP_RB;
        int tile = sid >> 5;
        jblk = (sid & 31) * 64;
        r0 = tile * BM;
        pw1 = h_sw1; pw3 = h_sw3; dstH = h_hs; dstride = SHIN; ni = SHIN;
    }

    int tid = threadIdx.x, wid = tid >> 5, lane = tid & 31;
    int wm = wid & 3, wn = wid >> 2;          // 4 x 2 warps
    int gq = lane >> 2, cq = lane & 3;

    if (tid < BM)
        s_tok[tid] = routed ? g_tok[r0 + min(tid, nvalid - 1)] : (r0 + tid);
    __syncthreads();

    const __half* gp[8];
    uint32_t so[8];
    uint32_t smu = smem_u32(sm);
    #pragma unroll
    for (int j = 0; j < 8; j++) {
        int id = tid + j * 256;
        int r = id >> 3;
        int s = id & 7;
        so[j] = (uint32_t)(r * RW + s * 4);
        if (r < 128) gp[j] = h_x + (size_t)s_tok[r] * DIM + s * 8;
        else {
            int rb = r - 128;
            if (rb < 64) gp[j] = pw1 + ((size_t)e * ni + jblk + rb) * DIM + s * 8;
            else         gp[j] = pw3 + ((size_t)e * ni + jblk + (rb - 64)) * DIM + s * 8;
        }
    }

    float acc1[2][4][4], acc3[2][4][4];
    #pragma unroll
    for (int i = 0; i < 2; i++)
        #pragma unroll
        for (int j = 0; j < 4; j++)
            #pragma unroll
            for (int q = 0; q < 4; q++) { acc1[i][j][q] = 0.f; acc3[i][j][q] = 0.f; }

    uint32_t laneOff = (uint32_t)((lane & 15) * (RW * 4) + ((lane & 16) ? 16 : 0));

    #pragma unroll
    for (int j = 0; j < 8; j++) cp16(smu + so[j] * 4, gp[j]);
    CP_COMMIT();
    #pragma unroll
    for (int j = 0; j < 8; j++) cp16(smu + (STGW + so[j]) * 4, gp[j] + KC);
    CP_COMMIT();

    for (int c = 0; c < NCH; c++) {
        int st = c % 3;
        cp_wait<1>();
        __syncthreads();

        uint32_t hA = smu + (uint32_t)(st * STGW) * 4;
        uint32_t hB = hA + 128 * RW * 4;

        #pragma unroll
        for (int ks = 0; ks < 4; ks++) {
            uint32_t ko = (uint32_t)(ks * 32);
            uint32_t a[2][4];
            #pragma unroll
            for (int i = 0; i < 2; i++)
                ldsm4(a[i], hA + (uint32_t)((wm * 32 + i * 16) * (RW * 4)) + ko + laneOff);
            uint32_t b1[2][4], b3[2][4];
            #pragma unroll
            for (int j2 = 0; j2 < 2; j2++) {
                int nb = wn * 32 + j2 * 16;
                ldsm4(b1[j2], hB + (uint32_t)(nb * (RW * 4)) + ko + laneOff);
                ldsm4(b3[j2], hB + (uint32_t)((64 + nb) * (RW * 4)) + ko + laneOff);
            }
            #pragma unroll
            for (int i = 0; i < 2; i++)
                #pragma unroll
                for (int j2 = 0; j2 < 2; j2++) {
                    mma16(acc1[i][j2 * 2 + 0], a[i], b1[j2][0], b1[j2][2]);
                    mma16(acc1[i][j2 * 2 + 1], a[i], b1[j2][1], b1[j2][3]);
                    mma16(acc3[i][j2 * 2 + 0], a[i], b3[j2][0], b3[j2][2]);
                    mma16(acc3[i][j2 * 2 + 1], a[i], b3[j2][1], b3[j2][3]);
                }
        }

        if (c + 2 < NCH) {
            int st2 = (c + 2) % 3;
            int kb = (c + 2) * KC;
            #pragma unroll
            for (int j = 0; j < 8; j++)
                cp16(smu + (st2 * STGW + so[j]) * 4, gp[j] + kb);
        }
        CP_COMMIT();
    }

    #pragma unroll
    for (int i = 0; i < 2; i++) {
        int rbase = wm * 32 + i * 16 + gq;
        #pragma unroll
        for (int j = 0; j < 4; j++) {
            int col = jblk + wn * 32 + j * 8 + 2 * cq;
            if (rbase < nvalid) {
                uint32_t o = pk16(silu_f(acc1[i][j][0]) * acc3[i][j][0],
                                  silu_f(acc1[i][j][1]) * acc3[i][j][1]);
                *(uint32_t*)(dstH + (size_t)(r0 + rbase) * dstride + col) = o;
            }
            if (rbase + 8 < nvalid) {
                uint32_t o = pk16(silu_f(acc1[i][j][2]) * acc3[i][j][2],
                                  silu_f(acc1[i][j][3]) * acc3[i][j][3]);
                *(uint32_t*)(dstH + (size_t)(r0 + rbase + 8) * dstride + col) = o;
            }
        }
    }
}

// ---------------- merged down kernel (fp16 operands, fp16 mma) ------------
__global__ __launch_bounds__(256, 2) void k_down(float* __restrict__ out) {
    extern __shared__ uint32_t sm[];
    __shared__ int   s_tok[BM];
    __shared__ float s_wtv[BM];

    int bid = blockIdx.x;
    int e = 0, r0, nvalid = BM, dblk, kd, nch;
    const __half* srcH; int sstride;
    const __half* pb;
    bool routed = bid < DN_RB;
    if (routed) {
        int tile = bid >> 4;
        if (tile >= g_ntiles) return;
        dblk = (bid & 15) * 128;
        e = g_tile_e[tile]; r0 = g_tile_r0[tile]; nvalid = g_tile_n[tile];
        srcH = h_h; sstride = INTER; kd = INTER; nch = INTER / KC;     // 16
        pb = h_w2;
    } else {
        int sid = bid - DN_RB;
        int tile = sid >> 4;
        dblk = (sid & 15) * 128;
        r0 = tile * BM;
        srcH = h_hs; sstride = SHIN; kd = SHIN; nch = SHIN / KC;       // 32
        pb = h_sw2;
    }

    int tid = threadIdx.x, wid = tid >> 5, lane = tid & 31;
    int wm = wid & 3, wn = wid >> 2;
    int gq = lane >> 2, cq = lane & 3;

    if (tid < BM) {
        if (routed) {
            int ok = tid < nvalid;
            s_tok[tid] = ok ? g_tok[r0 + tid] : 0;
            s_wtv[tid] = ok ? g_wt[r0 + tid]  : 0.f;
        } else { s_tok[tid] = r0 + tid; s_wtv[tid] = 1.f; }
    }
    __syncthreads();

    const __half* gp[8];
    uint32_t so[8];
    uint32_t smu = smem_u32(sm);
    #pragma unroll
    for (int j = 0; j < 8; j++) {
        int id = tid + j * 256;
        int r = id >> 3;
        int s = id & 7;
        so[j] = (uint32_t)(r * RW + s * 4);
        if (r < 128) gp[j] = srcH + (size_t)min(r0 + r, (routed ? NA : TT) - 1) * sstride + s * 8;
        else         gp[j] = pb + ((size_t)e * DIM + dblk + (r - 128)) * kd + s * 8;
    }

    float acc[2][8][4];
    #pragma unroll
    for (int i = 0; i < 2; i++)
        #pragma unroll
        for (int j = 0; j < 8; j++)
            #pragma unroll
            for (int q = 0; q < 4; q++) acc[i][j][q] = 0.f;

    uint32_t laneOff = (uint32_t)((lane & 15) * (RW * 4) + ((lane & 16) ? 16 : 0));

    #pragma unroll
    for (int j = 0; j < 8; j++) cp16(smu + so[j] * 4, gp[j]);
    CP_COMMIT();
    #pragma unroll
    for (int j = 0; j < 8; j++) cp16(smu + (STGW + so[j]) * 4, gp[j] + KC);
    CP_COMMIT();

    for (int c = 0; c < nch; c++) {
        int st = c % 3;
        cp_wait<1>();
        __syncthreads();

        uint32_t hA = smu + (uint32_t)(st * STGW) * 4;
        uint32_t hB = hA + 128 * RW * 4;

        #pragma unroll
        for (int ks = 0; ks < 4; ks++) {
            uint32_t ko = (uint32_t)(ks * 32);
            uint32_t a[2][4];
            #pragma unroll
            for (int i = 0; i < 2; i++)
                ldsm4(a[i], hA + (uint32_t)((wm * 32 + i * 16) * (RW * 4)) + ko + laneOff);
            uint32_t b[4][4];
            #pragma unroll
            for (int j2 = 0; j2 < 4; j2++)
                ldsm4(b[j2], hB + (uint32_t)((wn * 64 + j2 * 16) * (RW * 4)) + ko + laneOff);
            #pragma unroll
            for (int i = 0; i < 2; i++)
                #pragma unroll
                for (int j2 = 0; j2 < 4; j2++) {
                    mma16(acc[i][j2 * 2 + 0], a[i], b[j2][0], b[j2][2]);
                    mma16(acc[i][j2 * 2 + 1], a[i], b[j2][1], b[j2][3]);
                }
        }

        if (c + 2 < nch) {
            int st2 = (c + 2) % 3;
            int kb = (c + 2) * KC;
            #pragma unroll
            for (int j = 0; j < 8; j++)
                cp16(smu + (st2 * STGW + so[j]) * 4, gp[j] + kb);
        }
        CP_COMMIT();
    }

    #pragma unroll
    for (int i = 0; i < 2; i++) {
        int rbase = wm * 32 + i * 16 + gq;
        #pragma unroll
        for (int j = 0; j < 8; j++) {
            int col = dblk + wn * 64 + j * 8 + 2 * cq;
            #pragma unroll
            for (int half = 0; half < 2; half++) {
                int r = rbase + half * 8;
                if (r >= nvalid) continue;
                int tok = s_tok[r];
                float wt = s_wtv[r];
                float* dst = out + (size_t)tok * DIM + col;
                atomicAdd(dst + 0, acc[i][j][half * 2 + 0] * wt);
                atomicAdd(dst + 1, acc[i][j][half * 2 + 1] * wt);
            }
        }
    }
}

// ---------------- launch ----------------
extern "C" void kernel_launch(void* const* d_in, const int* in_sizes, int n_in,
                              void* d_out, int out_size) {
    const float* x   = (const float*)d_in[0];
    const float* gw  = (const float*)d_in[1];
    const float* w1  = (const float*)d_in[2];
    const float* w2  = (const float*)d_in[3];
    const float* w3  = (const float*)d_in[4];
    const float* sw1 = (const float*)d_in[5];
    const float* sw2 = (const float*)d_in[6];
    const float* sw3 = (const float*)d_in[7];
    float* out = (float*)d_out;

    void *p_w1, *p_w2, *p_w3, *p_sw1, *p_sw2, *p_sw3, *p_x;
    cudaGetSymbolAddress(&p_w1,  h_w1);
    cudaGetSymbolAddress(&p_w2,  h_w2);
    cudaGetSymbolAddress(&p_w3,  h_w3);
    cudaGetSymbolAddress(&p_sw1, h_sw1);
    cudaGetSymbolAddress(&p_sw2, h_sw2);
    cudaGetSymbolAddress(&p_sw3, h_sw3);
    cudaGetSymbolAddress(&p_x,   h_x);

    const int smBytes = 3 * STGW * 4;   // 110592
    cudaFuncSetAttribute((const void*)k_up,   cudaFuncAttributeMaxDynamicSharedMemorySize, smBytes);
    cudaFuncSetAttribute((const void*)k_down, cudaFuncAttributeMaxDynamicSharedMemorySize, smBytes);

    // convert weights + x to fp16 (ILP=4 streaming; 1024 float4 per block)
    const int NW = NEXP * INTER * DIM / 4;   // 16.78M float4 groups
    const int NS = SHIN * DIM / 4;           // 1.05M
    k_f2h<<<NW / 1024, 256>>>((const float4*)w1,  (uint2*)p_w1,  NW);
    k_f2h<<<NW / 1024, 256>>>((const float4*)w2,  (uint2*)p_w2,  NW);
    k_f2h<<<NW / 1024, 256>>>((const float4*)w3,  (uint2*)p_w3,  NW);
    k_f2h<<<NS / 1024, 256>>>((const float4*)sw1, (uint2*)p_sw1, NS);
    k_f2h<<<NS / 1024, 256>>>((const float4*)sw2, (uint2*)p_sw2, NS);
    k_f2h<<<NS / 1024, 256>>>((const float4*)sw3, (uint2*)p_sw3, NS);
    k_f2h<<<NS / 1024, 256>>>((const float4*)x,   (uint2*)p_x,   NS);

    k_zero<<<1, 32>>>();
    k_zero_out<<<(TT * DIM) / 1024, 256>>>(out);
    k_gate<<<TT, 128>>>(x, gw);
    k_build<<<1, 32>>>();
    k_scatter<<<NEXP, 256>>>();

    k_up<<<UP_RB + UP_SB, 256, smBytes>>>();
    k_down<<<DN_RB + DN_SB, 256, smBytes>>>(out);
}